// round 2
// baseline (speedup 1.0000x reference)
#include <cuda_runtime.h>

// ---------------------------------------------------------------------------
// B=2, N=512, D_IN=D_OUT=64, TEMP=100, POOL_K=0.5 -> kn=256
// ---------------------------------------------------------------------------
#define NB 2
#define NN 512
#define ND 64
#define KN 256
#define TEMP_INV (1.0f/100.0f)
#define BN_EPS 1e-5f
#define SELU_SCALE 1.0507009873554804934193349852946f
#define SELU_ALPHA 1.6732632423543772848170429916717f

// Scratch (allocation-free: __device__ globals)
__device__ float g_scores[NB*NN*NN];  // full score matrix (8 MB, L2-resident)
__device__ float g_h[NB*NN*ND];       // pre-BN h
__device__ float g_hw[NB*NN*ND];      // selu(h_bn) * w
__device__ float g_w[NB*NN];          // pool gate per row
__device__ float g_mean[ND];
__device__ float g_rstd[ND];

__device__ __forceinline__ float tanh_approx(float x) {
    float r;
    asm("tanh.approx.f32 %0, %1;" : "=f"(r) : "f"(x));
    return r;
}

// packed fp32x2 FMA: d = a*b + d  (lo/hi lanes independent)
__device__ __forceinline__ void ffma2(unsigned long long& d,
                                      unsigned long long a,
                                      unsigned long long b) {
    asm("fma.rn.f32x2 %0, %1, %2, %0;" : "+l"(d) : "l"(a), "l"(b));
}

union F2U { unsigned long long u; float2 f; };

// ---------------------------------------------------------------------------
// Phase 1: scores, upper triangle only (symmetry), written to both halves.
// Block (p, b) handles rows i = p and i = N-1-p; each computes j >= i.
// Chunks per block: (8 - p/64) + (8 - (511-p)/64) = 9 for every p -> balanced.
// Inner GEMM uses packed f32x2 FMA over d-pairs: A from Xs (d-contiguous),
// B from transposed Wt[e][d] (d-contiguous) -> no pack instructions.
// ---------------------------------------------------------------------------
__global__ __launch_bounds__(256) void kScores(
    const float* __restrict__ x,     // (B,N,64)
    const float* __restrict__ apw,   // (64,64) att_proj_w [d][e]
    const float* __restrict__ apb,   // (64)
    const float* __restrict__ awt)   // (64,1)
{
    __shared__ __align__(16) float Xs[64][72];   // j-chunk, [j][d]
    __shared__ __align__(16) float Wt[64][72];   // (diag(x_i)*W)^T : [e][d]
    __shared__ float spart[16][68];              // partial scores [te][j]
    __shared__ float xi_s[64], ab_s[64], aw_s[64];

    const int t = threadIdx.x;
    const int p = blockIdx.x;
    const int b = blockIdx.y;
    const float* xb = x + b * NN * ND;

    if (t < 64) { ab_s[t] = apb[t]; aw_s[t] = awt[t]; }

    const int te = t & 15;          // e-group: e = te + 16*ee
    const int tj = t >> 4;          // j-group of 4
    const int j0 = tj * 4;

    #pragma unroll 1
    for (int r = 0; r < 2; r++) {
        const int i = r ? (NN - 1 - p) : p;
        __syncthreads();                       // prev row fully consumed
        if (t < 64) xi_s[t] = xb[i * ND + t];
        __syncthreads();

        // Wt[e][d] = x_i[d] * W[d][e]
        #pragma unroll
        for (int k = 0; k < 16; k++) {
            int idx = t + k * 256;
            int d = idx >> 6, e = idx & 63;
            Wt[e][d] = xi_s[d] * apw[idx];
        }
        __syncthreads();

        for (int jc = i >> 6; jc < 8; jc++) {
            // coalesced load of 64-row j chunk
            #pragma unroll
            for (int k = 0; k < 4; k++) {
                int v = t + k * 256;
                int j = v >> 4, d4 = v & 15;
                *(float4*)&Xs[j][d4 * 4] =
                    *(const float4*)&xb[(jc * 64 + j) * ND + d4 * 4];
            }
            __syncthreads();

            // 4j x 4e register tile, packed even/odd-d accumulators
            unsigned long long acc[4][4] = {};
            #pragma unroll 4
            for (int d4 = 0; d4 < 16; d4++) {
                ulonglong2 bv[4];
                #pragma unroll
                for (int ee = 0; ee < 4; ee++)
                    bv[ee] = *(const ulonglong2*)&Wt[te + 16 * ee][d4 * 4];
                #pragma unroll
                for (int jj = 0; jj < 4; jj++) {
                    ulonglong2 av = *(const ulonglong2*)&Xs[j0 + jj][d4 * 4];
                    #pragma unroll
                    for (int ee = 0; ee < 4; ee++) {
                        ffma2(acc[jj][ee], av.x, bv[ee].x);
                        ffma2(acc[jj][ee], av.y, bv[ee].y);
                    }
                }
            }

            // tanh-reduce this thread's 4 e's
            #pragma unroll
            for (int jj = 0; jj < 4; jj++) {
                float s = 0.f;
                #pragma unroll
                for (int ee = 0; ee < 4; ee++) {
                    int e = te + 16 * ee;
                    F2U u; u.u = acc[jj][ee];
                    s += aw_s[e] * tanh_approx(u.f.x + u.f.y + ab_s[e]);
                }
                spart[te][j0 + jj] = s;
            }
            __syncthreads();

            if (t < 64) {
                int j = jc * 64 + t;
                if (j >= i) {
                    float s = 0.f;
                    #pragma unroll
                    for (int k = 0; k < 16; k++) s += spart[k][t];
                    g_scores[(b * NN + i) * NN + j] = s;
                    g_scores[(b * NN + j) * NN + i] = s;
                }
            }
            __syncthreads();
        }
    }
}

// ---------------------------------------------------------------------------
// Phase 2: per row i -> softmax(scores/TEMP), agg = attn @ X_b,
//          h = agg@pw + x_i@pwo + biases
// ---------------------------------------------------------------------------
__global__ __launch_bounds__(256) void kRow(
    const float* __restrict__ x,
    const float* __restrict__ pw,
    const float* __restrict__ pwb,
    const float* __restrict__ pwo,
    const float* __restrict__ pwob)
{
    __shared__ float scr[NN];
    __shared__ float red[256];
    __shared__ float aggp[256];
    __shared__ float agg_s[64];
    __shared__ float xi_s[64];

    const int t = threadIdx.x;
    const int i = blockIdx.x;
    const int b = blockIdx.y;
    const float* xb = x + b * NN * ND;
    const float* srow = g_scores + (b * NN + i) * NN;

    float s1 = srow[t], s2 = srow[t + 256];
    if (t < 64) xi_s[t] = xb[i * ND + t];

    // softmax over j with temperature
    red[t] = fmaxf(s1, s2);
    __syncthreads();
    for (int s = 128; s > 0; s >>= 1) {
        if (t < s) red[t] = fmaxf(red[t], red[t + s]);
        __syncthreads();
    }
    float mx = red[0];
    __syncthreads();
    float ea = __expf((s1 - mx) * TEMP_INV);
    float eb = __expf((s2 - mx) * TEMP_INV);
    red[t] = ea + eb;
    __syncthreads();
    for (int s = 128; s > 0; s >>= 1) {
        if (t < s) red[t] += red[t + s];
        __syncthreads();
    }
    float inv = 1.f / red[0];
    scr[t] = ea * inv;
    scr[t + 256] = eb * inv;
    __syncthreads();

    // agg[d] = sum_j attn[j] * X_b[j][d]
    {
        int d = t & 63, part = t >> 6;
        float a = 0.f;
        const float* xp = xb + part * 128 * ND + d;
        #pragma unroll 4
        for (int jj = 0; jj < 128; jj++)
            a += scr[part * 128 + jj] * xp[jj * ND];
        aggp[part * 64 + d] = a;
        __syncthreads();
        if (t < 64)
            agg_s[t] = aggp[t] + aggp[64 + t] + aggp[128 + t] + aggp[192 + t];
        __syncthreads();
    }

    if (t < 64) {
        float hacc = pwb[t] + pwob[t];
        #pragma unroll 8
        for (int dd = 0; dd < 64; dd++)
            hacc += agg_s[dd] * pw[dd * 64 + t] + xi_s[dd] * pwo[dd * 64 + t];
        g_h[(b * NN + i) * ND + t] = hacc;
    }
}

// ---------------------------------------------------------------------------
// Kernel B: deterministic batch-norm stats (1024 rows x 64 features)
// ---------------------------------------------------------------------------
__global__ __launch_bounds__(256) void kernelB() {
    __shared__ float s1[256], s2[256];
    int t = threadIdx.x;
    int e = t & 63, part = t >> 6;
    float sum = 0.f, sq = 0.f;
    #pragma unroll 4
    for (int r = part; r < NB * NN; r += 4) {
        float v = g_h[r * ND + e];
        sum += v;
        sq += v * v;
    }
    s1[t] = sum;
    s2[t] = sq;
    __syncthreads();
    if (t < 64) {
        float S = s1[t] + s1[64 + t] + s1[128 + t] + s1[192 + t];
        float Q = s2[t] + s2[64 + t] + s2[128 + t] + s2[192 + t];
        float mean = S * (1.f / (NB * NN));
        float var = fmaxf(Q * (1.f / (NB * NN)) - mean * mean, 0.f);
        g_mean[t] = mean;
        g_rstd[t] = rsqrtf(var + BN_EPS);
    }
}

// ---------------------------------------------------------------------------
// Kernel C1: BN + SELU + pool gate; store hw = selu_h * w and w.
// ---------------------------------------------------------------------------
__global__ __launch_bounds__(64) void kernelC1(
    const float* __restrict__ bn_g, const float* __restrict__ bn_b,
    const float* __restrict__ pool_w, const float* __restrict__ pool_b)
{
    __shared__ float pr[2];
    int r = blockIdx.x;
    int e = threadIdx.x;
    float h = g_h[r * ND + e];
    float hn = (h - g_mean[e]) * g_rstd[e] * bn_g[e] + bn_b[e];
    float s = hn > 0.f ? SELU_SCALE * hn
                       : SELU_SCALE * SELU_ALPHA * (__expf(hn) - 1.f);
    float p = s * pool_w[e];
    #pragma unroll
    for (int o = 16; o > 0; o >>= 1) p += __shfl_down_sync(0xffffffffu, p, o);
    if ((e & 31) == 0) pr[e >> 5] = p;
    __syncthreads();
    float logit = pr[0] + pr[1] + pool_b[0];
    float w = 1.f / (1.f + __expf(-logit));
    g_hw[r * ND + e] = s * w;
    if (e == 0) g_w[r] = w;
}

// ---------------------------------------------------------------------------
// Kernel C2: stable rank selection (top_k order: value desc, index asc),
// single barrier, scatter top-256 rows.
// ---------------------------------------------------------------------------
__global__ __launch_bounds__(512) void kernelC2(float* __restrict__ out) {
    __shared__ float sv[NN];
    int t = threadIdx.x;
    int b = blockIdx.x;
    float v = g_w[b * NN + t];
    sv[t] = v;
    __syncthreads();

    int rank = 0;
    #pragma unroll 8
    for (int j = 0; j < NN; j++) {
        float u = sv[j];
        rank += (u > v) || (u == v && j < t);
    }

    if (rank < KN) {
        const float* sp = g_hw + (b * NN + t) * ND;
        float* dp = out + (b * KN + rank) * ND;
        #pragma unroll
        for (int q = 0; q < 16; q++)
            *(float4*)&dp[q * 4] = *(const float4*)&sp[q * 4];
    }
}

// ---------------------------------------------------------------------------
// Launch (graph-capturable)
// ---------------------------------------------------------------------------
extern "C" void kernel_launch(void* const* d_in, const int* in_sizes, int n_in,
                              void* d_out, int out_size)
{
    const float* x     = (const float*)d_in[0];
    const float* apw   = (const float*)d_in[1];
    const float* apb   = (const float*)d_in[2];
    const float* awt   = (const float*)d_in[3];
    const float* pw    = (const float*)d_in[4];
    const float* pwb   = (const float*)d_in[5];
    const float* pwo   = (const float*)d_in[6];
    const float* pwob  = (const float*)d_in[7];
    const float* bn_g  = (const float*)d_in[8];
    const float* bn_b  = (const float*)d_in[9];
    const float* poolw = (const float*)d_in[10];
    const float* poolb = (const float*)d_in[11];
    float* out = (float*)d_out;

    kScores<<<dim3(NN / 2, NB), 256>>>(x, apw, apb, awt);
    kRow<<<dim3(NN, NB), 256>>>(x, pw, pwb, pwo, pwob);
    kernelB<<<1, 256>>>();
    kernelC1<<<NB * NN, 64>>>(bn_g, bn_b, poolw, poolb);
    kernelC2<<<NB, 512>>>(out);
}

// round 3
// speedup vs baseline: 1.2857x; 1.2857x over previous
#include <cuda_runtime.h>

// ---------------------------------------------------------------------------
// B=2, N=512, D_IN=D_OUT=64, TEMP=100, POOL_K=0.5 -> kn=256
// ---------------------------------------------------------------------------
#define NB 2
#define NN 512
#define ND 64
#define KN 256
#define TEMP_INV (1.0f/100.0f)
#define BN_EPS 1e-5f
#define SELU_SCALE 1.0507009873554804934193349852946f
#define SELU_ALPHA 1.6732632423543772848170429916717f

// Scratch (allocation-free: __device__ globals)
__device__ float g_scores[NB*NN*NN];  // full score matrix (2 MB, L2-resident)
__device__ float g_h[NB*NN*ND];       // pre-BN h
__device__ float g_hw[NB*NN*ND];      // selu(h_bn) * w
__device__ float g_w[NB*NN];          // pool gate per row
__device__ float g_mean[ND];
__device__ float g_rstd[ND];

__device__ __forceinline__ float tanh_approx(float x) {
    float r;
    asm("tanh.approx.f32 %0, %1;" : "=f"(r) : "f"(x));
    return r;
}

// no-op dummies: shift ncu's captured launch index so the 4th launch = kScores
__global__ void kDummy() {}

// ---------------------------------------------------------------------------
// Phase 1: scores, upper triangle only (symmetry), written to both halves.
// Block (p, b) handles rows i = p and i = N-1-p; each computes j >= i
// (chunk granularity). Chunks per block = 9 for every p -> balanced.
// Inner loop: SCALAR FFMA 4j x 4e register tile (sm_100a has no native FFMA2;
// fma.rn.f32x2 is emulated and was a pessimization in round 2).
// ---------------------------------------------------------------------------
__global__ __launch_bounds__(256) void kScores(
    const float* __restrict__ x,     // (B,N,64)
    const float* __restrict__ apw,   // (64,64) att_proj_w [d][e]
    const float* __restrict__ apb,   // (64)
    const float* __restrict__ awt)   // (64,1)
{
    __shared__ __align__(16) float Xs[64][68];   // j-chunk, [j][d]
    __shared__ __align__(16) float Wi[64*64];    // diag(x_i)*W : [d][e]
    __shared__ float spart[16][68];              // partial scores [te][j]
    __shared__ float xi_s[64], ab_s[64], aw_s[64];

    const int t = threadIdx.x;
    const int p = blockIdx.x;
    const int b = blockIdx.y;
    const float* xb = x + b * NN * ND;

    if (t < 64) { ab_s[t] = apb[t]; aw_s[t] = awt[t]; }

    const int te = t & 15;          // 16 e-groups of 4 (e-contiguous)
    const int tj = t >> 4;          // 16 j-groups of 4
    const int e0 = te * 4;
    const int j0 = tj * 4;

    #pragma unroll 1
    for (int r = 0; r < 2; r++) {
        const int i = r ? (NN - 1 - p) : p;
        __syncthreads();                       // prev iter fully consumed
        if (t < 64) xi_s[t] = xb[i * ND + t];
        __syncthreads();

        // Wi[d][e] = x_i[d] * W[d][e]
        #pragma unroll
        for (int k = 0; k < 16; k++) {
            int idx = t + k * 256;
            Wi[idx] = xi_s[idx >> 6] * apw[idx];
        }
        __syncthreads();

        for (int jc = i >> 6; jc < 8; jc++) {
            // coalesced load of 64-row j chunk
            #pragma unroll
            for (int k = 0; k < 4; k++) {
                int v = t + k * 256;
                int j = v >> 4, d4 = v & 15;
                *(float4*)&Xs[j][d4 * 4] =
                    *(const float4*)&xb[(jc * 64 + j) * ND + d4 * 4];
            }
            __syncthreads();

            // scalar register-tiled GEMM: 4j x 4e per thread
            float acc[4][4] = {};
            #pragma unroll 8
            for (int d = 0; d < 64; d++) {
                float4 bv = *(const float4*)&Wi[d * 64 + e0];
                #pragma unroll
                for (int jj = 0; jj < 4; jj++) {
                    float a = Xs[j0 + jj][d];
                    acc[jj][0] += a * bv.x;
                    acc[jj][1] += a * bv.y;
                    acc[jj][2] += a * bv.z;
                    acc[jj][3] += a * bv.w;
                }
            }

            // tanh-reduce this thread's 4 e's
            #pragma unroll
            for (int jj = 0; jj < 4; jj++) {
                float s = 0.f;
                #pragma unroll
                for (int q = 0; q < 4; q++)
                    s += aw_s[e0 + q] * tanh_approx(acc[jj][q] + ab_s[e0 + q]);
                spart[te][j0 + jj] = s;
            }
            __syncthreads();

            if (t < 64) {
                int j = jc * 64 + t;
                if (j >= i) {
                    float s = 0.f;
                    #pragma unroll
                    for (int k = 0; k < 16; k++) s += spart[k][t];
                    g_scores[(b * NN + i) * NN + j] = s;
                    g_scores[(b * NN + j) * NN + i] = s;
                }
            }
            __syncthreads();
        }
    }
}

// ---------------------------------------------------------------------------
// Phase 2: per row i -> softmax(scores/TEMP), agg = attn @ X_b,
//          h = agg@pw + x_i@pwo + biases.  Shuffle-based reductions.
// ---------------------------------------------------------------------------
__global__ __launch_bounds__(256) void kRow(
    const float* __restrict__ x,
    const float* __restrict__ pw,
    const float* __restrict__ pwb,
    const float* __restrict__ pwo,
    const float* __restrict__ pwob)
{
    __shared__ float scr[NN];
    __shared__ float red[8];
    __shared__ float aggp[256];
    __shared__ float agg_s[64];
    __shared__ float xi_s[64];

    const int t = threadIdx.x;
    const int lane = t & 31, warp = t >> 5;
    const int i = blockIdx.x;
    const int b = blockIdx.y;
    const float* xb = x + b * NN * ND;
    const float* srow = g_scores + (b * NN + i) * NN;

    float s1 = srow[t], s2 = srow[t + 256];
    if (t < 64) xi_s[t] = xb[i * ND + t];

    // ---- max reduce (warp shuffle + 8-slot smem) ----
    float m = fmaxf(s1, s2);
    #pragma unroll
    for (int o = 16; o > 0; o >>= 1)
        m = fmaxf(m, __shfl_xor_sync(0xffffffffu, m, o));
    if (lane == 0) red[warp] = m;
    __syncthreads();
    float mx = red[0];
    #pragma unroll
    for (int k = 1; k < 8; k++) mx = fmaxf(mx, red[k]);
    __syncthreads();

    float ea = __expf((s1 - mx) * TEMP_INV);
    float eb = __expf((s2 - mx) * TEMP_INV);

    // ---- sum reduce ----
    float sm = ea + eb;
    #pragma unroll
    for (int o = 16; o > 0; o >>= 1)
        sm += __shfl_xor_sync(0xffffffffu, sm, o);
    if (lane == 0) red[warp] = sm;
    __syncthreads();
    float tot = red[0];
    #pragma unroll
    for (int k = 1; k < 8; k++) tot += red[k];
    float inv = 1.f / tot;
    scr[t] = ea * inv;
    scr[t + 256] = eb * inv;
    __syncthreads();

    // agg[d] = sum_j attn[j] * X_b[j][d]
    {
        int d = t & 63, part = t >> 6;
        float a = 0.f;
        const float* xp = xb + part * 128 * ND + d;
        #pragma unroll 4
        for (int jj = 0; jj < 128; jj++)
            a += scr[part * 128 + jj] * xp[jj * ND];
        aggp[part * 64 + d] = a;
        __syncthreads();
        if (t < 64)
            agg_s[t] = aggp[t] + aggp[64 + t] + aggp[128 + t] + aggp[192 + t];
        __syncthreads();
    }

    if (t < 64) {
        float hacc = pwb[t] + pwob[t];
        #pragma unroll 8
        for (int dd = 0; dd < 64; dd++)
            hacc += agg_s[dd] * pw[dd * 64 + t] + xi_s[dd] * pwo[dd * 64 + t];
        g_h[(b * NN + i) * ND + t] = hacc;
    }
}

// ---------------------------------------------------------------------------
// Kernel B: deterministic batch-norm stats (1024 rows x 64 features)
// ---------------------------------------------------------------------------
__global__ __launch_bounds__(256) void kernelB() {
    __shared__ float s1[256], s2[256];
    int t = threadIdx.x;
    int e = t & 63, part = t >> 6;
    float sum = 0.f, sq = 0.f;
    #pragma unroll 4
    for (int r = part; r < NB * NN; r += 4) {
        float v = g_h[r * ND + e];
        sum += v;
        sq += v * v;
    }
    s1[t] = sum;
    s2[t] = sq;
    __syncthreads();
    if (t < 64) {
        float S = s1[t] + s1[64 + t] + s1[128 + t] + s1[192 + t];
        float Q = s2[t] + s2[64 + t] + s2[128 + t] + s2[192 + t];
        float mean = S * (1.f / (NB * NN));
        float var = fmaxf(Q * (1.f / (NB * NN)) - mean * mean, 0.f);
        g_mean[t] = mean;
        g_rstd[t] = rsqrtf(var + BN_EPS);
    }
}

// ---------------------------------------------------------------------------
// Kernel C1: BN + SELU + pool gate; store hw = selu_h * w and w.
// ---------------------------------------------------------------------------
__global__ __launch_bounds__(64) void kernelC1(
    const float* __restrict__ bn_g, const float* __restrict__ bn_b,
    const float* __restrict__ pool_w, const float* __restrict__ pool_b)
{
    __shared__ float pr[2];
    int r = blockIdx.x;
    int e = threadIdx.x;
    float h = g_h[r * ND + e];
    float hn = (h - g_mean[e]) * g_rstd[e] * bn_g[e] + bn_b[e];
    float s = hn > 0.f ? SELU_SCALE * hn
                       : SELU_SCALE * SELU_ALPHA * (__expf(hn) - 1.f);
    float p = s * pool_w[e];
    #pragma unroll
    for (int o = 16; o > 0; o >>= 1) p += __shfl_down_sync(0xffffffffu, p, o);
    if ((e & 31) == 0) pr[e >> 5] = p;
    __syncthreads();
    float logit = pr[0] + pr[1] + pool_b[0];
    float w = 1.f / (1.f + __expf(-logit));
    g_hw[r * ND + e] = s * w;
    if (e == 0) g_w[r] = w;
}

// ---------------------------------------------------------------------------
// Kernel C2: stable rank selection (top_k order: value desc, index asc),
// single barrier, scatter top-256 rows.
// ---------------------------------------------------------------------------
__global__ __launch_bounds__(512) void kernelC2(float* __restrict__ out) {
    __shared__ float sv[NN];
    int t = threadIdx.x;
    int b = blockIdx.x;
    float v = g_w[b * NN + t];
    sv[t] = v;
    __syncthreads();

    int rank = 0;
    #pragma unroll 8
    for (int j = 0; j < NN; j++) {
        float u = sv[j];
        rank += (u > v) || (u == v && j < t);
    }

    if (rank < KN) {
        const float* sp = g_hw + (b * NN + t) * ND;
        float* dp = out + (b * KN + rank) * ND;
        #pragma unroll
        for (int q = 0; q < 16; q++)
            *(float4*)&dp[q * 4] = *(const float4*)&sp[q * 4];
    }
}

// ---------------------------------------------------------------------------
// Launch (graph-capturable). 3 no-op dummies first so the profiler's captured
// launch (observed: always the 4th) is kScores.
// ---------------------------------------------------------------------------
extern "C" void kernel_launch(void* const* d_in, const int* in_sizes, int n_in,
                              void* d_out, int out_size)
{
    const float* x     = (const float*)d_in[0];
    const float* apw   = (const float*)d_in[1];
    const float* apb   = (const float*)d_in[2];
    const float* awt   = (const float*)d_in[3];
    const float* pw    = (const float*)d_in[4];
    const float* pwb   = (const float*)d_in[5];
    const float* pwo   = (const float*)d_in[6];
    const float* pwob  = (const float*)d_in[7];
    const float* bn_g  = (const float*)d_in[8];
    const float* bn_b  = (const float*)d_in[9];
    const float* poolw = (const float*)d_in[10];
    const float* poolb = (const float*)d_in[11];
    float* out = (float*)d_out;

    kDummy<<<1, 32>>>();
    kDummy<<<1, 32>>>();
    kDummy<<<1, 32>>>();
    kScores<<<dim3(NN / 2, NB), 256>>>(x, apw, apb, awt);
    kRow<<<dim3(NN, NB), 256>>>(x, pw, pwb, pwo, pwob);
    kernelB<<<1, 256>>>();
    kernelC1<<<NB * NN, 64>>>(bn_g, bn_b, poolw, poolb);
    kernelC2<<<NB, 512>>>(out);
}

// round 4
// speedup vs baseline: 1.8817x; 1.4635x over previous
#include <cuda_runtime.h>
#include <cstdint>

// ---------------------------------------------------------------------------
// B=2, N=512, D_IN=D_OUT=64, TEMP=100, POOL_K=0.5 -> kn=256
// ---------------------------------------------------------------------------
#define NB 2
#define NN 512
#define ND 64
#define KN 256
#define TEMP_INV (1.0f/100.0f)
#define BN_EPS 1e-5f
#define SELU_SCALE 1.0507009873554804934193349852946f
#define SELU_ALPHA 1.6732632423543772848170429916717f

__device__ float g_scores[NB*NN*NN];
__device__ float g_h[NB*NN*ND];
__device__ float g_hw[NB*NN*ND];
__device__ float g_w[NB*NN];
__device__ float g_mean[ND];
__device__ float g_rstd[ND];

__device__ __forceinline__ float tanh_approx(float x) {
    float r;
    asm("tanh.approx.f32 %0, %1;" : "=f"(r) : "f"(x));
    return r;
}
__device__ __forceinline__ uint32_t to_tf32(float f) {
    uint32_t u;
    asm("cvt.rna.tf32.f32 %0, %1;" : "=r"(u) : "f"(f));
    return u;
}
__device__ __forceinline__ void mma_tf32(float c[4], uint32_t a0, uint32_t a1,
                                         uint32_t a2, uint32_t a3,
                                         uint32_t b0, uint32_t b1) {
    asm("mma.sync.aligned.m16n8k8.row.col.f32.tf32.tf32.f32 "
        "{%0,%1,%2,%3}, {%4,%5,%6,%7}, {%8,%9}, {%0,%1,%2,%3};"
        : "+f"(c[0]), "+f"(c[1]), "+f"(c[2]), "+f"(c[3])
        : "r"(a0), "r"(a1), "r"(a2), "r"(a3), "r"(b0), "r"(b1));
}

__global__ void kDummy() {}

// ---------------------------------------------------------------------------
// Phase 1 (tensor cores): scores upper triangle via symmetry.
// Block (p,b) -> rows i=p and i=511-p, chunks j>=i (9 chunk-GEMMs/block).
// Chunk GEMM Z = Xs(64x64) @ Wi(64x64) via m16n8k8 tf32 mma:
//   warp w: j-tile = (w&3)*16, e-half = (w>>2)*32 (4 n8-tiles), 8 k-steps.
// Epilogue in C-fragments: s_j = sum_e aw[e]*tanh(z+ab[e]).
// ---------------------------------------------------------------------------
__global__ __launch_bounds__(256) void kScores(
    const float* __restrict__ x,
    const float* __restrict__ apw,
    const float* __restrict__ apb,
    const float* __restrict__ awt)
{
    __shared__ __align__(16) uint32_t Xs[64][68];  // tf32 bits, [j][d]
    __shared__ uint32_t Wi[64][72];                // tf32 bits, [d][e]
    __shared__ float spart[2][64];
    __shared__ float xi_s[64], ab_s[64], aw_s[64];

    const int t = threadIdx.x;
    const int p = blockIdx.x;
    const int b = blockIdx.y;
    const float* xb = x + b * NN * ND;

    const int warp = t >> 5, lane = t & 31;
    const int jt = (warp & 3) * 16;   // j-tile base
    const int eh = (warp >> 2) * 32;  // e-half base
    const int qr = lane >> 2;         // group row 0..7
    const int qc = lane & 3;          // thread-in-group 0..3

    if (t < 64) { ab_s[t] = apb[t]; aw_s[t] = awt[t]; }

    #pragma unroll 1
    for (int r = 0; r < 2; r++) {
        const int i = r ? (NN - 1 - p) : p;
        __syncthreads();
        if (t < 64) xi_s[t] = xb[i * ND + t];
        __syncthreads();

        // Wi[d][e] = tf32(x_i[d] * W[d][e])
        #pragma unroll
        for (int k = 0; k < 16; k++) {
            int idx = t + k * 256;
            Wi[idx >> 6][idx & 63] = to_tf32(xi_s[idx >> 6] * apw[idx]);
        }

        for (int jc = i >> 6; jc < 8; jc++) {
            // fill Xs chunk (tf32 bits), coalesced float4 loads
            #pragma unroll
            for (int k = 0; k < 4; k++) {
                int v = t + k * 256;
                int j = v >> 4, d4 = v & 15;
                float4 f = *(const float4*)&xb[(jc * 64 + j) * ND + d4 * 4];
                uint4 u = { to_tf32(f.x), to_tf32(f.y), to_tf32(f.z), to_tf32(f.w) };
                *(uint4*)&Xs[j][d4 * 4] = u;
            }
            __syncthreads();

            float acc[4][4] = {};
            #pragma unroll
            for (int ks = 0; ks < 8; ks++) {
                const int k0 = ks * 8;
                uint32_t a0 = Xs[jt + qr][k0 + qc];
                uint32_t a1 = Xs[jt + qr + 8][k0 + qc];
                uint32_t a2 = Xs[jt + qr][k0 + qc + 4];
                uint32_t a3 = Xs[jt + qr + 8][k0 + qc + 4];
                #pragma unroll
                for (int et = 0; et < 4; et++) {
                    uint32_t b0 = Wi[k0 + qc][eh + et * 8 + qr];
                    uint32_t b1 = Wi[k0 + qc + 4][eh + et * 8 + qr];
                    mma_tf32(acc[et], a0, a1, a2, a3, b0, b1);
                }
            }

            // epilogue: tanh-weight-reduce over this thread's 8 e's, 2 j rows
            float s0 = 0.f, s1 = 0.f;
            #pragma unroll
            for (int et = 0; et < 4; et++) {
                int e = eh + et * 8 + 2 * qc;
                s0 += aw_s[e]     * tanh_approx(acc[et][0] + ab_s[e]);
                s0 += aw_s[e + 1] * tanh_approx(acc[et][1] + ab_s[e + 1]);
                s1 += aw_s[e]     * tanh_approx(acc[et][2] + ab_s[e]);
                s1 += aw_s[e + 1] * tanh_approx(acc[et][3] + ab_s[e + 1]);
            }
            // reduce over the 4 threads of the quad (cols)
            s0 += __shfl_xor_sync(0xffffffffu, s0, 1);
            s0 += __shfl_xor_sync(0xffffffffu, s0, 2);
            s1 += __shfl_xor_sync(0xffffffffu, s1, 1);
            s1 += __shfl_xor_sync(0xffffffffu, s1, 2);
            if (qc == 0) {
                spart[warp >> 2][jt + qr] = s0;
                spart[warp >> 2][jt + qr + 8] = s1;
            }
            __syncthreads();

            if (t < 64) {
                int j = jc * 64 + t;
                if (j >= i) {
                    float s = spart[0][t] + spart[1][t];
                    g_scores[(b * NN + i) * NN + j] = s;
                    g_scores[(b * NN + j) * NN + i] = s;
                }
            }
            __syncthreads();
        }
    }
}

// ---------------------------------------------------------------------------
// Phase 2: 8 rows per block (one per warp), X_b chunk shared in smem.
// Warp-local softmax; agg accumulated per warp; then h = agg@pw + x@pwo + b.
// ---------------------------------------------------------------------------
__global__ __launch_bounds__(256) void kRow(
    const float* __restrict__ x,
    const float* __restrict__ pw,
    const float* __restrict__ pwb,
    const float* __restrict__ pwo,
    const float* __restrict__ pwob)
{
    __shared__ __align__(16) float Xs[64][68];
    __shared__ float attn_s[8][512];
    __shared__ float agg_s[8][64];

    const int t = threadIdx.x;
    const int warp = t >> 5, lane = t & 31;
    const int b = blockIdx.y;
    const int i = blockIdx.x * 8 + warp;
    const float* xb = x + b * NN * ND;
    const float* srow = g_scores + (b * NN + i) * NN;

    // warp-local softmax over 512 scores
    float sv[16];
    float m = -1e30f;
    #pragma unroll
    for (int q = 0; q < 16; q++) {
        sv[q] = srow[q * 32 + lane];
        m = fmaxf(m, sv[q]);
    }
    #pragma unroll
    for (int o = 16; o > 0; o >>= 1)
        m = fmaxf(m, __shfl_xor_sync(0xffffffffu, m, o));
    float sum = 0.f;
    #pragma unroll
    for (int q = 0; q < 16; q++) {
        sv[q] = __expf((sv[q] - m) * TEMP_INV);
        sum += sv[q];
    }
    #pragma unroll
    for (int o = 16; o > 0; o >>= 1)
        sum += __shfl_xor_sync(0xffffffffu, sum, o);
    float inv = 1.f / sum;
    #pragma unroll
    for (int q = 0; q < 16; q++)
        attn_s[warp][q * 32 + lane] = sv[q] * inv;

    // agg[d] accumulated as d=lane and d=lane+32
    float a0 = 0.f, a1 = 0.f;
    for (int jc = 0; jc < 8; jc++) {
        __syncthreads();
        #pragma unroll
        for (int k = 0; k < 4; k++) {
            int v = t + k * 256;
            int j = v >> 4, d4 = v & 15;
            *(float4*)&Xs[j][d4 * 4] =
                *(const float4*)&xb[(jc * 64 + j) * ND + d4 * 4];
        }
        __syncthreads();
        #pragma unroll 8
        for (int j = 0; j < 64; j++) {
            float a = attn_s[warp][jc * 64 + j];
            a0 += a * Xs[j][lane];
            a1 += a * Xs[j][lane + 32];
        }
    }
    agg_s[warp][lane] = a0;
    agg_s[warp][lane + 32] = a1;
    __syncwarp();

    // h[e] for e=lane, e=lane+32
    float h0 = pwb[lane] + pwob[lane];
    float h1 = pwb[lane + 32] + pwob[lane + 32];
    const float* xi = xb + i * ND;
    #pragma unroll 8
    for (int d = 0; d < 64; d++) {
        float ag = agg_s[warp][d];
        float xv = xi[d];
        h0 += ag * pw[d * 64 + lane]      + xv * pwo[d * 64 + lane];
        h1 += ag * pw[d * 64 + lane + 32] + xv * pwo[d * 64 + lane + 32];
    }
    g_h[(b * NN + i) * ND + lane] = h0;
    g_h[(b * NN + i) * ND + lane + 32] = h1;
}

// ---------------------------------------------------------------------------
// Kernel B: deterministic batch-norm stats (1024 rows x 64 features)
// ---------------------------------------------------------------------------
__global__ __launch_bounds__(256) void kernelB() {
    __shared__ float s1[256], s2[256];
    int t = threadIdx.x;
    int e = t & 63, part = t >> 6;
    float sum = 0.f, sq = 0.f;
    #pragma unroll 4
    for (int r = part; r < NB * NN; r += 4) {
        float v = g_h[r * ND + e];
        sum += v;
        sq += v * v;
    }
    s1[t] = sum;
    s2[t] = sq;
    __syncthreads();
    if (t < 64) {
        float S = s1[t] + s1[64 + t] + s1[128 + t] + s1[192 + t];
        float Q = s2[t] + s2[64 + t] + s2[128 + t] + s2[192 + t];
        float mean = S * (1.f / (NB * NN));
        float var = fmaxf(Q * (1.f / (NB * NN)) - mean * mean, 0.f);
        g_mean[t] = mean;
        g_rstd[t] = rsqrtf(var + BN_EPS);
    }
}

// ---------------------------------------------------------------------------
// Kernel C1: BN + SELU + pool gate; 4 rows per 256-thread block.
// ---------------------------------------------------------------------------
__global__ __launch_bounds__(256) void kernelC1(
    const float* __restrict__ bn_g, const float* __restrict__ bn_b,
    const float* __restrict__ pool_w, const float* __restrict__ pool_b)
{
    __shared__ float pr[8];
    int t = threadIdx.x;
    int rr = t >> 6, e = t & 63;
    int r = blockIdx.x * 4 + rr;
    float h = g_h[r * ND + e];
    float hn = (h - g_mean[e]) * g_rstd[e] * bn_g[e] + bn_b[e];
    float s = hn > 0.f ? SELU_SCALE * hn
                       : SELU_SCALE * SELU_ALPHA * (__expf(hn) - 1.f);
    float p = s * pool_w[e];
    #pragma unroll
    for (int o = 16; o > 0; o >>= 1) p += __shfl_down_sync(0xffffffffu, p, o);
    if ((t & 31) == 0) pr[t >> 5] = p;
    __syncthreads();
    float logit = pr[rr * 2] + pr[rr * 2 + 1] + pool_b[0];
    float w = 1.f / (1.f + __expf(-logit));
    g_hw[r * ND + e] = s * w;
    if (e == 0) g_w[r] = w;
}

// ---------------------------------------------------------------------------
// Kernel C2: stable rank selection (value desc, index asc), scatter top-256.
// ---------------------------------------------------------------------------
__global__ __launch_bounds__(512) void kernelC2(float* __restrict__ out) {
    __shared__ float sv[NN];
    int t = threadIdx.x;
    int b = blockIdx.x;
    float v = g_w[b * NN + t];
    sv[t] = v;
    __syncthreads();

    int rank = 0;
    #pragma unroll 8
    for (int j = 0; j < NN; j++) {
        float u = sv[j];
        rank += (u > v) || (u == v && j < t);
    }

    if (rank < KN) {
        const float* sp = g_hw + (b * NN + t) * ND;
        float* dp = out + (b * KN + rank) * ND;
        #pragma unroll
        for (int q = 0; q < 16; q++)
            *(float4*)&dp[q * 4] = *(const float4*)&sp[q * 4];
    }
}

// ---------------------------------------------------------------------------
// Launch (graph-capturable). 3 dummies keep ncu's captured launch on kScores.
// ---------------------------------------------------------------------------
extern "C" void kernel_launch(void* const* d_in, const int* in_sizes, int n_in,
                              void* d_out, int out_size)
{
    const float* x     = (const float*)d_in[0];
    const float* apw   = (const float*)d_in[1];
    const float* apb   = (const float*)d_in[2];
    const float* awt   = (const float*)d_in[3];
    const float* pw    = (const float*)d_in[4];
    const float* pwb   = (const float*)d_in[5];
    const float* pwo   = (const float*)d_in[6];
    const float* pwob  = (const float*)d_in[7];
    const float* bn_g  = (const float*)d_in[8];
    const float* bn_b  = (const float*)d_in[9];
    const float* poolw = (const float*)d_in[10];
    const float* poolb = (const float*)d_in[11];
    float* out = (float*)d_out;

    kDummy<<<1, 32>>>();
    kDummy<<<1, 32>>>();
    kDummy<<<1, 32>>>();
    kScores<<<dim3(NN / 2, NB), 256>>>(x, apw, apb, awt);
    kRow<<<dim3(NN / 8, NB), 256>>>(x, pw, pwb, pwo, pwob);
    kernelB<<<1, 256>>>();
    kernelC1<<<NB * NN / 4, 256>>>(bn_g, bn_b, poolw, poolb);
    kernelC2<<<NB, 512>>>(out);
}

// round 7
// speedup vs baseline: 2.0226x; 1.0749x over previous
#include <cuda_runtime.h>
#include <cstdint>

// ---------------------------------------------------------------------------
// B=2, N=512, D_IN=D_OUT=64, TEMP=100, POOL_K=0.5 -> kn=256
// ---------------------------------------------------------------------------
#define NB 2
#define NN 512
#define ND 64
#define KN 256
#define TEMP_INV (1.0f/100.0f)
#define BN_EPS 1e-5f
#define SELU_SCALE 1.0507009873554804934193349852946f
#define SELU_ALPHA 1.6732632423543772848170429916717f

__device__ float g_scores[NB*NN*NN];
__device__ float g_h[NB*NN*ND];
__device__ float g_part[128*128];   // per-kRow-block partial BN stats

__device__ __forceinline__ float tanh_approx(float x) {
    float r;
    asm("tanh.approx.f32 %0, %1;" : "=f"(r) : "f"(x));
    return r;
}
__device__ __forceinline__ uint32_t to_tf32(float f) {
    uint32_t u;
    asm("cvt.rna.tf32.f32 %0, %1;" : "=r"(u) : "f"(f));
    return u;
}
__device__ __forceinline__ void mma_tf32(float c[4], uint32_t a0, uint32_t a1,
                                         uint32_t a2, uint32_t a3,
                                         uint32_t b0, uint32_t b1) {
    asm("mma.sync.aligned.m16n8k8.row.col.f32.tf32.tf32.f32 "
        "{%0,%1,%2,%3}, {%4,%5,%6,%7}, {%8,%9}, {%0,%1,%2,%3};"
        : "+f"(c[0]), "+f"(c[1]), "+f"(c[2]), "+f"(c[3])
        : "r"(a0), "r"(a1), "r"(a2), "r"(a3), "r"(b0), "r"(b1));
}

__global__ void kDummy() {}

// ---------------------------------------------------------------------------
// Phase 1 (tensor cores, round-4 proven version): scores upper triangle via
// symmetry. Block (p,b) -> rows i=p, 511-p; chunks j>=i. 64x64x64 tf32 GEMM.
// Warp w: j-tile (w&3)*16, e-half (w>>2)*32 (4 n8-tiles), 8 k-steps.
// Fragments via scalar LDS (no 32-bit ldmatrix exists).
// ---------------------------------------------------------------------------
__global__ __launch_bounds__(256) void kScores(
    const float* __restrict__ x,
    const float* __restrict__ apw,
    const float* __restrict__ apb,
    const float* __restrict__ awt)
{
    __shared__ __align__(16) uint32_t Xs[64][68];  // tf32 bits, [j][d]
    __shared__ uint32_t Wi[64][72];                // tf32 bits, [d][e]
    __shared__ float spart[2][64];
    __shared__ float xi_s[64], ab_s[64], aw_s[64];

    const int t = threadIdx.x;
    const int p = blockIdx.x;
    const int b = blockIdx.y;
    const float* xb = x + b * NN * ND;

    const int warp = t >> 5, lane = t & 31;
    const int jt = (warp & 3) * 16;
    const int eh = (warp >> 2) * 32;
    const int qr = lane >> 2, qc = lane & 3;

    if (t < 64) { ab_s[t] = apb[t]; aw_s[t] = awt[t]; }

    #pragma unroll 1
    for (int r = 0; r < 2; r++) {
        const int i = r ? (NN - 1 - p) : p;
        __syncthreads();
        if (t < 64) xi_s[t] = xb[i * ND + t];
        __syncthreads();

        // Wi[d][e] = tf32(x_i[d] * W[d][e])
        #pragma unroll
        for (int k = 0; k < 16; k++) {
            int idx = t + k * 256;
            Wi[idx >> 6][idx & 63] = to_tf32(xi_s[idx >> 6] * apw[idx]);
        }

        for (int jc = i >> 6; jc < 8; jc++) {
            #pragma unroll
            for (int k = 0; k < 4; k++) {
                int v = t + k * 256;
                int j = v >> 4, d4 = v & 15;
                float4 f = *(const float4*)&xb[(jc * 64 + j) * ND + d4 * 4];
                uint4 u = { to_tf32(f.x), to_tf32(f.y), to_tf32(f.z), to_tf32(f.w) };
                *(uint4*)&Xs[j][d4 * 4] = u;
            }
            __syncthreads();

            float acc[4][4] = {};
            #pragma unroll
            for (int ks = 0; ks < 8; ks++) {
                const int k0 = ks * 8;
                uint32_t a0 = Xs[jt + qr][k0 + qc];
                uint32_t a1 = Xs[jt + qr + 8][k0 + qc];
                uint32_t a2 = Xs[jt + qr][k0 + qc + 4];
                uint32_t a3 = Xs[jt + qr + 8][k0 + qc + 4];
                #pragma unroll
                for (int et = 0; et < 4; et++) {
                    uint32_t b0 = Wi[k0 + qc][eh + et * 8 + qr];
                    uint32_t b1 = Wi[k0 + qc + 4][eh + et * 8 + qr];
                    mma_tf32(acc[et], a0, a1, a2, a3, b0, b1);
                }
            }

            // epilogue: s_j = sum_e aw[e]*tanh(z+ab[e]) over this warp's 32 e
            float s0 = 0.f, s1 = 0.f;
            #pragma unroll
            for (int et = 0; et < 4; et++) {
                int e = eh + et * 8 + 2 * qc;
                s0 += aw_s[e]     * tanh_approx(acc[et][0] + ab_s[e]);
                s0 += aw_s[e + 1] * tanh_approx(acc[et][1] + ab_s[e + 1]);
                s1 += aw_s[e]     * tanh_approx(acc[et][2] + ab_s[e]);
                s1 += aw_s[e + 1] * tanh_approx(acc[et][3] + ab_s[e + 1]);
            }
            s0 += __shfl_xor_sync(0xffffffffu, s0, 1);
            s0 += __shfl_xor_sync(0xffffffffu, s0, 2);
            s1 += __shfl_xor_sync(0xffffffffu, s1, 1);
            s1 += __shfl_xor_sync(0xffffffffu, s1, 2);
            if (qc == 0) {
                spart[warp >> 2][jt + qr] = s0;
                spart[warp >> 2][jt + qr + 8] = s1;
            }
            __syncthreads();

            if (t < 64) {
                int j = jc * 64 + t;
                if (j >= i) {
                    float s = spart[0][t] + spart[1][t];
                    g_scores[(b * NN + i) * NN + j] = s;
                    g_scores[(b * NN + j) * NN + i] = s;
                }
            }
            __syncthreads();
        }
    }
}

// ---------------------------------------------------------------------------
// Phase 2: 8 rows per block (one per warp). Softmax warp-local, agg via
// smem-staged X chunks, h = agg@pw + x@pwo + biases. Also emits this block's
// BN partial sums (sum h, sum h^2 per feature) -> g_part.
// ---------------------------------------------------------------------------
__global__ __launch_bounds__(256) void kRow(
    const float* __restrict__ x,
    const float* __restrict__ pw,
    const float* __restrict__ pwb,
    const float* __restrict__ pwo,
    const float* __restrict__ pwob)
{
    __shared__ __align__(16) float Xs[64][68];
    __shared__ float attn_s[8][512];
    __shared__ float agg_s[8][64];
    __shared__ float hs[8][64];

    const int t = threadIdx.x;
    const int warp = t >> 5, lane = t & 31;
    const int b = blockIdx.y;
    const int i = blockIdx.x * 8 + warp;
    const float* xb = x + b * NN * ND;
    const float* srow = g_scores + (b * NN + i) * NN;

    float sv[16];
    float m = -1e30f;
    #pragma unroll
    for (int q = 0; q < 16; q++) {
        sv[q] = srow[q * 32 + lane];
        m = fmaxf(m, sv[q]);
    }
    #pragma unroll
    for (int o = 16; o > 0; o >>= 1)
        m = fmaxf(m, __shfl_xor_sync(0xffffffffu, m, o));
    float sum = 0.f;
    #pragma unroll
    for (int q = 0; q < 16; q++) {
        sv[q] = __expf((sv[q] - m) * TEMP_INV);
        sum += sv[q];
    }
    #pragma unroll
    for (int o = 16; o > 0; o >>= 1)
        sum += __shfl_xor_sync(0xffffffffu, sum, o);
    float inv = 1.f / sum;
    #pragma unroll
    for (int q = 0; q < 16; q++)
        attn_s[warp][q * 32 + lane] = sv[q] * inv;

    float a0 = 0.f, a1 = 0.f;
    for (int jc = 0; jc < 8; jc++) {
        __syncthreads();
        #pragma unroll
        for (int k = 0; k < 4; k++) {
            int v = t + k * 256;
            int j = v >> 4, d4 = v & 15;
            *(float4*)&Xs[j][d4 * 4] =
                *(const float4*)&xb[(jc * 64 + j) * ND + d4 * 4];
        }
        __syncthreads();
        #pragma unroll 8
        for (int j = 0; j < 64; j++) {
            float a = attn_s[warp][jc * 64 + j];
            a0 += a * Xs[j][lane];
            a1 += a * Xs[j][lane + 32];
        }
    }
    agg_s[warp][lane] = a0;
    agg_s[warp][lane + 32] = a1;
    __syncwarp();

    float h0 = pwb[lane] + pwob[lane];
    float h1 = pwb[lane + 32] + pwob[lane + 32];
    const float* xi = xb + i * ND;
    #pragma unroll 8
    for (int d = 0; d < 64; d++) {
        float ag = agg_s[warp][d];
        float xv = xi[d];
        h0 += ag * pw[d * 64 + lane]      + xv * pwo[d * 64 + lane];
        h1 += ag * pw[d * 64 + lane + 32] + xv * pwo[d * 64 + lane + 32];
    }
    g_h[(b * NN + i) * ND + lane] = h0;
    g_h[(b * NN + i) * ND + lane + 32] = h1;
    hs[warp][lane] = h0;
    hs[warp][lane + 32] = h1;
    __syncthreads();

    // partial BN stats for this block's 8 rows
    if (t < 128) {
        int f = t & 63;
        float s = 0.f;
        if (t < 64) {
            #pragma unroll
            for (int w = 0; w < 8; w++) s += hs[w][f];
        } else {
            #pragma unroll
            for (int w = 0; w < 8; w++) { float v = hs[w][f]; s += v * v; }
        }
        g_part[(b * 64 + blockIdx.x) * 128 + t] = s;
    }
}

// ---------------------------------------------------------------------------
// kTail (one block per batch, 512 threads = one row each):
//   1) reduce g_part -> mean/rstd  (both blocks do it; deterministic)
//   2) per-row BN + SELU + pool gate, register-resident
//   3) stable rank selection (value desc, index asc), scatter row to out[rank]
// ---------------------------------------------------------------------------
__global__ __launch_bounds__(512) void kTail(
    const float* __restrict__ bn_g, const float* __restrict__ bn_b,
    const float* __restrict__ pool_w, const float* __restrict__ pool_b,
    float* __restrict__ out)
{
    __shared__ float red1[512], red2[512];
    __shared__ float a_s[64], c_s[64], pw_s[64];
    __shared__ float wv_s[512];

    const int t = threadIdx.x;
    const int b = blockIdx.x;

    // ---- stats reduce: feature f = t&63, group = t>>6 (8 groups x 16 blks)
    {
        int f = t & 63, grp = t >> 6;
        float s = 0.f, q = 0.f;
        #pragma unroll 4
        for (int blk = grp; blk < 128; blk += 8) {
            s += g_part[blk * 128 + f];
            q += g_part[blk * 128 + 64 + f];
        }
        red1[t] = s;
        red2[t] = q;
        __syncthreads();
        if (t < 64) {
            float S = 0.f, Q = 0.f;
            #pragma unroll
            for (int g = 0; g < 8; g++) { S += red1[g * 64 + t]; Q += red2[g * 64 + t]; }
            float mean = S * (1.f / (NB * NN));
            float var = fmaxf(Q * (1.f / (NB * NN)) - mean * mean, 0.f);
            float a = rsqrtf(var + BN_EPS) * bn_g[t];
            a_s[t] = a;
            c_s[t] = bn_b[t] - mean * a;
            pw_s[t] = pool_w[t];
        }
        __syncthreads();
    }

    // ---- row phase: BN + SELU + pool logit, all in registers
    const float* hr = g_h + (b * NN + t) * ND;
    float4 hv[16];
    #pragma unroll
    for (int q = 0; q < 16; q++) hv[q] = *(const float4*)&hr[q * 4];

    float p = 0.f;
    #pragma unroll
    for (int q = 0; q < 16; q++) {
        #pragma unroll
        for (int c = 0; c < 4; c++) {
            int e = q * 4 + c;
            float v = (c == 0 ? hv[q].x : c == 1 ? hv[q].y : c == 2 ? hv[q].z : hv[q].w);
            float hn = v * a_s[e] + c_s[e];
            float s = hn > 0.f ? SELU_SCALE * hn
                               : SELU_SCALE * SELU_ALPHA * (__expf(hn) - 1.f);
            p += s * pw_s[e];
            if (c == 0) hv[q].x = s; else if (c == 1) hv[q].y = s;
            else if (c == 2) hv[q].z = s; else hv[q].w = s;
        }
    }
    float w = 1.f / (1.f + __expf(-(p + pool_b[0])));
    wv_s[t] = w;
    __syncthreads();

    // ---- stable rank (top_k order: value desc, index asc)
    int rank = 0;
    #pragma unroll 8
    for (int j = 0; j < NN; j++) {
        float u = wv_s[j];
        rank += (u > w) || (u == w && j < t);
    }

    if (rank < KN) {
        float* dp = out + (b * KN + rank) * ND;
        #pragma unroll
        for (int q = 0; q < 16; q++) {
            float4 o = hv[q];
            o.x *= w; o.y *= w; o.z *= w; o.w *= w;
            *(float4*)&dp[q * 4] = o;
        }
    }
}

// ---------------------------------------------------------------------------
// Launch (graph-capturable). 3 dummies keep ncu's captured launch on kScores.
// ---------------------------------------------------------------------------
extern "C" void kernel_launch(void* const* d_in, const int* in_sizes, int n_in,
                              void* d_out, int out_size)
{
    const float* x     = (const float*)d_in[0];
    const float* apw   = (const float*)d_in[1];
    const float* apb   = (const float*)d_in[2];
    const float* awt   = (const float*)d_in[3];
    const float* pw    = (const float*)d_in[4];
    const float* pwb   = (const float*)d_in[5];
    const float* pwo   = (const float*)d_in[6];
    const float* pwob  = (const float*)d_in[7];
    const float* bn_g  = (const float*)d_in[8];
    const float* bn_b  = (const float*)d_in[9];
    const float* poolw = (const float*)d_in[10];
    const float* poolb = (const float*)d_in[11];
    float* out = (float*)d_out;

    kDummy<<<1, 32>>>();
    kDummy<<<1, 32>>>();
    kDummy<<<1, 32>>>();
    kScores<<<dim3(NN / 2, NB), 256>>>(x, apw, apb, awt);
    kRow<<<dim3(NN / 8, NB), 256>>>(x, pw, pwb, pwo, pwob);
    kTail<<<NB, 512>>>(bn_g, bn_b, poolw, poolb, out);
}

// round 8
// speedup vs baseline: 2.2867x; 1.1306x over previous
#include <cuda_runtime.h>
#include <cuda_bf16.h>
#include <cstdint>

// ---------------------------------------------------------------------------
// B=2, N=512, D_IN=D_OUT=64, TEMP=100, POOL_K=0.5 -> kn=256
// ---------------------------------------------------------------------------
#define NB 2
#define NN 512
#define ND 64
#define KN 256
#define TEMP_INV (1.0f/100.0f)
#define BN_EPS 1e-5f
#define SELU_SCALE 1.0507009873554804934193349852946f
#define SELU_ALPHA 1.6732632423543772848170429916717f

__device__ float g_scores[NB*NN*NN];
__device__ float g_h[NB*NN*ND];
__device__ float g_part[128*128];   // per-kRow-block partial BN stats

__device__ __forceinline__ float tanh_approx(float x) {
    float r;
    asm("tanh.approx.f32 %0, %1;" : "=f"(r) : "f"(x));
    return r;
}
__device__ __forceinline__ void mma_bf16(float c[4], const uint32_t a[4],
                                         uint32_t b0, uint32_t b1) {
    asm("mma.sync.aligned.m16n8k16.row.col.f32.bf16.bf16.f32 "
        "{%0,%1,%2,%3}, {%4,%5,%6,%7}, {%8,%9}, {%0,%1,%2,%3};"
        : "+f"(c[0]), "+f"(c[1]), "+f"(c[2]), "+f"(c[3])
        : "r"(a[0]), "r"(a[1]), "r"(a[2]), "r"(a[3]), "r"(b0), "r"(b1));
}
__device__ __forceinline__ void ldsm_x4(uint32_t r[4], uint32_t addr) {
    asm volatile("ldmatrix.sync.aligned.m8n8.x4.shared.b16 {%0,%1,%2,%3}, [%4];"
        : "=r"(r[0]), "=r"(r[1]), "=r"(r[2]), "=r"(r[3]) : "r"(addr));
}

__global__ void kDummy() {}

// ---------------------------------------------------------------------------
// Phase 1 (bf16 tensor cores + ldmatrix): scores upper triangle via symmetry.
// Block (p,b) -> rows i=p, 511-p; chunks j>=i. 64x64x64 GEMM in bf16,
// fp32 accumulate. Warp w: j-tile (w&3)*16, e-half (w>>2)*32, 4 k16-steps.
// Xs[j][d] and Wt[e][d] bf16, row stride 72 (144B -> ldmatrix conflict-free).
// Per k-step: 3 ldmatrix.x4 + 4 mma.m16n8k16.
// ---------------------------------------------------------------------------
__global__ __launch_bounds__(256) void kScores(
    const float* __restrict__ x,
    const float* __restrict__ apw,
    const float* __restrict__ apb,
    const float* __restrict__ awt)
{
    __shared__ __align__(16) __nv_bfloat16 Xs[64][72];  // [j][d]
    __shared__ __align__(16) __nv_bfloat16 Wt[64][72];  // [e][d]
    __shared__ float spart[2][64];
    __shared__ float xi_s[64], ab_s[64], aw_s[64];

    const int t = threadIdx.x;
    const int p = blockIdx.x;
    const int b = blockIdx.y;
    const float* xb = x + b * NN * ND;

    const int warp = t >> 5, lane = t & 31;
    const int jt = (warp & 3) * 16;
    const int eh = (warp >> 2) * 32;
    const int qr = lane >> 2, qc = lane & 3;

    if (t < 64) { ab_s[t] = apb[t]; aw_s[t] = awt[t]; }

    const uint32_t xsBase = (uint32_t)__cvta_generic_to_shared(&Xs[0][0]);
    const uint32_t wtBase = (uint32_t)__cvta_generic_to_shared(&Wt[0][0]);
    // A: 4 matrices = {rows jt..+7, jt+8..+15} x {k 0..7, 8..15}
    const uint32_t aAddr = xsBase + (jt + (lane & 15)) * 144 + (lane >> 4) * 16;
    // B group 1: matrices {e rows eh..+7 (klo,khi), eh+8..+15 (klo,khi)}
    const uint32_t bAddr1 = wtBase +
        (eh + (lane >> 4) * 8 + (lane & 7)) * 144 + ((lane >> 3) & 1) * 16;
    const uint32_t bAddr2 = bAddr1 + 16 * 144;   // e-tiles 2,3

    #pragma unroll 1
    for (int r = 0; r < 2; r++) {
        const int i = r ? (NN - 1 - p) : p;
        __syncthreads();
        if (t < 64) xi_s[t] = xb[i * ND + t];
        __syncthreads();

        // Wt[e][d] = bf16(x_i[d] * W[d][e]);  apw idx = d*64+e
        #pragma unroll
        for (int k = 0; k < 16; k++) {
            int idx = t + k * 256;
            int d = idx >> 6, e = idx & 63;
            Wt[e][d] = __float2bfloat16(xi_s[d] * apw[idx]);
        }

        for (int jc = i >> 6; jc < 8; jc++) {
            // fill Xs chunk: float4 -> 2x bf16x2, 8B stores
            #pragma unroll
            for (int k = 0; k < 4; k++) {
                int v = t + k * 256;
                int j = v >> 4, d4 = v & 15;
                float4 f = *(const float4*)&xb[(jc * 64 + j) * ND + d4 * 4];
                __nv_bfloat162 lo = __float22bfloat162_rn(make_float2(f.x, f.y));
                __nv_bfloat162 hi = __float22bfloat162_rn(make_float2(f.z, f.w));
                uint2 u = { *(uint32_t*)&lo, *(uint32_t*)&hi };
                *(uint2*)&Xs[j][d4 * 4] = u;
            }
            __syncthreads();

            float acc[4][4] = {};
            #pragma unroll
            for (int ks = 0; ks < 4; ks++) {
                uint32_t a[4], b01[4], b23[4];
                ldsm_x4(a,   aAddr  + ks * 32);
                ldsm_x4(b01, bAddr1 + ks * 32);
                ldsm_x4(b23, bAddr2 + ks * 32);
                mma_bf16(acc[0], a, b01[0], b01[1]);
                mma_bf16(acc[1], a, b01[2], b01[3]);
                mma_bf16(acc[2], a, b23[0], b23[1]);
                mma_bf16(acc[3], a, b23[2], b23[3]);
            }

            // epilogue: s_j = sum_e aw[e]*tanh(z+ab[e]) over this warp's 32 e
            float s0 = 0.f, s1 = 0.f;
            #pragma unroll
            for (int et = 0; et < 4; et++) {
                int e = eh + et * 8 + 2 * qc;
                s0 += aw_s[e]     * tanh_approx(acc[et][0] + ab_s[e]);
                s0 += aw_s[e + 1] * tanh_approx(acc[et][1] + ab_s[e + 1]);
                s1 += aw_s[e]     * tanh_approx(acc[et][2] + ab_s[e]);
                s1 += aw_s[e + 1] * tanh_approx(acc[et][3] + ab_s[e + 1]);
            }
            s0 += __shfl_xor_sync(0xffffffffu, s0, 1);
            s0 += __shfl_xor_sync(0xffffffffu, s0, 2);
            s1 += __shfl_xor_sync(0xffffffffu, s1, 1);
            s1 += __shfl_xor_sync(0xffffffffu, s1, 2);
            if (qc == 0) {
                spart[warp >> 2][jt + qr] = s0;
                spart[warp >> 2][jt + qr + 8] = s1;
            }
            __syncthreads();

            if (t < 64) {
                int j = jc * 64 + t;
                if (j >= i) {
                    float s = spart[0][t] + spart[1][t];
                    g_scores[(b * NN + i) * NN + j] = s;
                    g_scores[(b * NN + j) * NN + i] = s;
                }
            }
            __syncthreads();
        }
    }
}

// ---------------------------------------------------------------------------
// Phase 2: 8 rows per block (one per warp). Softmax warp-local, agg via
// smem-staged X chunks, h = agg@pw + x@pwo + biases. Emits per-block BN
// partial sums -> g_part.
// ---------------------------------------------------------------------------
__global__ __launch_bounds__(256) void kRow(
    const float* __restrict__ x,
    const float* __restrict__ pw,
    const float* __restrict__ pwb,
    const float* __restrict__ pwo,
    const float* __restrict__ pwob)
{
    __shared__ __align__(16) float Xs[64][68];
    __shared__ float attn_s[8][512];
    __shared__ float agg_s[8][64];
    __shared__ float hs[8][64];

    const int t = threadIdx.x;
    const int warp = t >> 5, lane = t & 31;
    const int b = blockIdx.y;
    const int i = blockIdx.x * 8 + warp;
    const float* xb = x + b * NN * ND;
    const float* srow = g_scores + (b * NN + i) * NN;

    float sv[16];
    float m = -1e30f;
    #pragma unroll
    for (int q = 0; q < 16; q++) {
        sv[q] = srow[q * 32 + lane];
        m = fmaxf(m, sv[q]);
    }
    #pragma unroll
    for (int o = 16; o > 0; o >>= 1)
        m = fmaxf(m, __shfl_xor_sync(0xffffffffu, m, o));
    float sum = 0.f;
    #pragma unroll
    for (int q = 0; q < 16; q++) {
        sv[q] = __expf((sv[q] - m) * TEMP_INV);
        sum += sv[q];
    }
    #pragma unroll
    for (int o = 16; o > 0; o >>= 1)
        sum += __shfl_xor_sync(0xffffffffu, sum, o);
    float inv = 1.f / sum;
    #pragma unroll
    for (int q = 0; q < 16; q++)
        attn_s[warp][q * 32 + lane] = sv[q] * inv;

    float a0 = 0.f, a1 = 0.f;
    for (int jc = 0; jc < 8; jc++) {
        __syncthreads();
        #pragma unroll
        for (int k = 0; k < 4; k++) {
            int v = t + k * 256;
            int j = v >> 4, d4 = v & 15;
            *(float4*)&Xs[j][d4 * 4] =
                *(const float4*)&xb[(jc * 64 + j) * ND + d4 * 4];
        }
        __syncthreads();
        #pragma unroll 8
        for (int j = 0; j < 64; j++) {
            float a = attn_s[warp][jc * 64 + j];
            a0 += a * Xs[j][lane];
            a1 += a * Xs[j][lane + 32];
        }
    }
    agg_s[warp][lane] = a0;
    agg_s[warp][lane + 32] = a1;
    __syncwarp();

    float h0 = pwb[lane] + pwob[lane];
    float h1 = pwb[lane + 32] + pwob[lane + 32];
    const float* xi = xb + i * ND;
    #pragma unroll 8
    for (int d = 0; d < 64; d++) {
        float ag = agg_s[warp][d];
        float xv = xi[d];
        h0 += ag * pw[d * 64 + lane]      + xv * pwo[d * 64 + lane];
        h1 += ag * pw[d * 64 + lane + 32] + xv * pwo[d * 64 + lane + 32];
    }
    g_h[(b * NN + i) * ND + lane] = h0;
    g_h[(b * NN + i) * ND + lane + 32] = h1;
    hs[warp][lane] = h0;
    hs[warp][lane + 32] = h1;
    __syncthreads();

    if (t < 128) {
        int f = t & 63;
        float s = 0.f;
        if (t < 64) {
            #pragma unroll
            for (int w = 0; w < 8; w++) s += hs[w][f];
        } else {
            #pragma unroll
            for (int w = 0; w < 8; w++) { float v = hs[w][f]; s += v * v; }
        }
        g_part[(b * 64 + blockIdx.x) * 128 + t] = s;
    }
}

// ---------------------------------------------------------------------------
// kTail (one block per batch, 512 threads = one row each):
// stats reduce -> BN+SELU+pool in registers -> stable rank -> scatter.
// ---------------------------------------------------------------------------
__global__ __launch_bounds__(512) void kTail(
    const float* __restrict__ bn_g, const float* __restrict__ bn_b,
    const float* __restrict__ pool_w, const float* __restrict__ pool_b,
    float* __restrict__ out)
{
    __shared__ float red1[512], red2[512];
    __shared__ float a_s[64], c_s[64], pw_s[64];
    __shared__ float wv_s[512];

    const int t = threadIdx.x;
    const int b = blockIdx.x;

    {
        int f = t & 63, grp = t >> 6;
        float s = 0.f, q = 0.f;
        #pragma unroll 4
        for (int blk = grp; blk < 128; blk += 8) {
            s += g_part[blk * 128 + f];
            q += g_part[blk * 128 + 64 + f];
        }
        red1[t] = s;
        red2[t] = q;
        __syncthreads();
        if (t < 64) {
            float S = 0.f, Q = 0.f;
            #pragma unroll
            for (int g = 0; g < 8; g++) { S += red1[g * 64 + t]; Q += red2[g * 64 + t]; }
            float mean = S * (1.f / (NB * NN));
            float var = fmaxf(Q * (1.f / (NB * NN)) - mean * mean, 0.f);
            float a = rsqrtf(var + BN_EPS) * bn_g[t];
            a_s[t] = a;
            c_s[t] = bn_b[t] - mean * a;
            pw_s[t] = pool_w[t];
        }
        __syncthreads();
    }

    const float* hr = g_h + (b * NN + t) * ND;
    float4 hv[16];
    #pragma unroll
    for (int q = 0; q < 16; q++) hv[q] = *(const float4*)&hr[q * 4];

    float p = 0.f;
    #pragma unroll
    for (int q = 0; q < 16; q++) {
        #pragma unroll
        for (int c = 0; c < 4; c++) {
            int e = q * 4 + c;
            float v = (c == 0 ? hv[q].x : c == 1 ? hv[q].y : c == 2 ? hv[q].z : hv[q].w);
            float hn = v * a_s[e] + c_s[e];
            float s = hn > 0.f ? SELU_SCALE * hn
                               : SELU_SCALE * SELU_ALPHA * (__expf(hn) - 1.f);
            p += s * pw_s[e];
            if (c == 0) hv[q].x = s; else if (c == 1) hv[q].y = s;
            else if (c == 2) hv[q].z = s; else hv[q].w = s;
        }
    }
    float w = 1.f / (1.f + __expf(-(p + pool_b[0])));
    wv_s[t] = w;
    __syncthreads();

    int rank = 0;
    #pragma unroll 8
    for (int j = 0; j < NN; j++) {
        float u = wv_s[j];
        rank += (u > w) || (u == w && j < t);
    }

    if (rank < KN) {
        float* dp = out + (b * KN + rank) * ND;
        #pragma unroll
        for (int q = 0; q < 16; q++) {
            float4 o = hv[q];
            o.x *= w; o.y *= w; o.z *= w; o.w *= w;
            *(float4*)&dp[q * 4] = o;
        }
    }
}

// ---------------------------------------------------------------------------
// Launch (graph-capturable). 2 dummies -> ncu's captured launch (#4) = kRow.
// ---------------------------------------------------------------------------
extern "C" void kernel_launch(void* const* d_in, const int* in_sizes, int n_in,
                              void* d_out, int out_size)
{
    const float* x     = (const float*)d_in[0];
    const float* apw   = (const float*)d_in[1];
    const float* apb   = (const float*)d_in[2];
    const float* awt   = (const float*)d_in[3];
    const float* pw    = (const float*)d_in[4];
    const float* pwb   = (const float*)d_in[5];
    const float* pwo   = (const float*)d_in[6];
    const float* pwob  = (const float*)d_in[7];
    const float* bn_g  = (const float*)d_in[8];
    const float* bn_b  = (const float*)d_in[9];
    const float* poolw = (const float*)d_in[10];
    const float* poolb = (const float*)d_in[11];
    float* out = (float*)d_out;

    kDummy<<<1, 32>>>();
    kDummy<<<1, 32>>>();
    kScores<<<dim3(NN / 2, NB), 256>>>(x, apw, apb, awt);
    kRow<<<dim3(NN / 8, NB), 256>>>(x, pw, pwb, pwo, pwob);
    kTail<<<NB, 512>>>(bn_g, bn_b, poolw, poolb, out);
}

// round 11
// speedup vs baseline: 2.3143x; 1.0121x over previous
#include <cuda_runtime.h>
#include <cuda_bf16.h>
#include <cstdint>

// ---------------------------------------------------------------------------
// B=2, N=512, D_IN=D_OUT=64, TEMP=100, POOL_K=0.5 -> kn=256
// ---------------------------------------------------------------------------
#define NB 2
#define NN 512
#define ND 64
#define KN 256
#define TEMP_INV (1.0f/100.0f)
#define BN_EPS 1e-5f
#define SELU_SCALE 1.0507009873554804934193349852946f
#define SELU_ALPHA 1.6732632423543772848170429916717f

__device__ float g_scores[NB*NN*NN];
__device__ float g_h[NB*NN*ND];
__device__ float g_part[64*128];    // per-kAgg-block partial BN stats

__device__ __forceinline__ float tanh_approx(float x) {
    float r;
    asm("tanh.approx.f32 %0, %1;" : "=f"(r) : "f"(x));
    return r;
}
__device__ __forceinline__ uint32_t to_tf32(float f) {
    uint32_t u;
    asm("cvt.rna.tf32.f32 %0, %1;" : "=r"(u) : "f"(f));
    return u;
}
__device__ __forceinline__ void mma_tf32(float c[4], uint32_t a0, uint32_t a1,
                                         uint32_t a2, uint32_t a3,
                                         uint32_t b0, uint32_t b1) {
    asm("mma.sync.aligned.m16n8k8.row.col.f32.tf32.tf32.f32 "
        "{%0,%1,%2,%3}, {%4,%5,%6,%7}, {%8,%9}, {%0,%1,%2,%3};"
        : "+f"(c[0]), "+f"(c[1]), "+f"(c[2]), "+f"(c[3])
        : "r"(a0), "r"(a1), "r"(a2), "r"(a3), "r"(b0), "r"(b1));
}
__device__ __forceinline__ void mma_bf16(float c[4], const uint32_t a[4],
                                         uint32_t b0, uint32_t b1) {
    asm("mma.sync.aligned.m16n8k16.row.col.f32.bf16.bf16.f32 "
        "{%0,%1,%2,%3}, {%4,%5,%6,%7}, {%8,%9}, {%0,%1,%2,%3};"
        : "+f"(c[0]), "+f"(c[1]), "+f"(c[2]), "+f"(c[3])
        : "r"(a[0]), "r"(a[1]), "r"(a[2]), "r"(a[3]), "r"(b0), "r"(b1));
}
__device__ __forceinline__ void ldsm_x4(uint32_t r[4], uint32_t addr) {
    asm volatile("ldmatrix.sync.aligned.m8n8.x4.shared.b16 {%0,%1,%2,%3}, [%4];"
        : "=r"(r[0]), "=r"(r[1]), "=r"(r[2]), "=r"(r[3]) : "r"(addr));
}

__global__ void kDummy() {}

// ---------------------------------------------------------------------------
// Phase 1 (bf16 tensor cores + ldmatrix, proven at rel_err 1.15e-6):
// scores upper triangle via symmetry. Unchanged from round 8.
// ---------------------------------------------------------------------------
__global__ __launch_bounds__(256) void kScores(
    const float* __restrict__ x,
    const float* __restrict__ apw,
    const float* __restrict__ apb,
    const float* __restrict__ awt)
{
    __shared__ __align__(16) __nv_bfloat16 Xs[64][72];  // [j][d]
    __shared__ __align__(16) __nv_bfloat16 Wt[64][72];  // [e][d]
    __shared__ float spart[2][64];
    __shared__ float xi_s[64], ab_s[64], aw_s[64];

    const int t = threadIdx.x;
    const int p = blockIdx.x;
    const int b = blockIdx.y;
    const float* xb = x + b * NN * ND;

    const int warp = t >> 5, lane = t & 31;
    const int jt = (warp & 3) * 16;
    const int eh = (warp >> 2) * 32;
    const int qr = lane >> 2, qc = lane & 3;

    if (t < 64) { ab_s[t] = apb[t]; aw_s[t] = awt[t]; }

    const uint32_t xsBase = (uint32_t)__cvta_generic_to_shared(&Xs[0][0]);
    const uint32_t wtBase = (uint32_t)__cvta_generic_to_shared(&Wt[0][0]);
    const uint32_t aAddr = xsBase + (jt + (lane & 15)) * 144 + (lane >> 4) * 16;
    const uint32_t bAddr1 = wtBase +
        (eh + (lane >> 4) * 8 + (lane & 7)) * 144 + ((lane >> 3) & 1) * 16;
    const uint32_t bAddr2 = bAddr1 + 16 * 144;

    #pragma unroll 1
    for (int r = 0; r < 2; r++) {
        const int i = r ? (NN - 1 - p) : p;
        __syncthreads();
        if (t < 64) xi_s[t] = xb[i * ND + t];
        __syncthreads();

        #pragma unroll
        for (int k = 0; k < 16; k++) {
            int idx = t + k * 256;
            int d = idx >> 6, e = idx & 63;
            Wt[e][d] = __float2bfloat16(xi_s[d] * apw[idx]);
        }

        for (int jc = i >> 6; jc < 8; jc++) {
            #pragma unroll
            for (int k = 0; k < 4; k++) {
                int v = t + k * 256;
                int j = v >> 4, d4 = v & 15;
                float4 f = *(const float4*)&xb[(jc * 64 + j) * ND + d4 * 4];
                __nv_bfloat162 lo = __float22bfloat162_rn(make_float2(f.x, f.y));
                __nv_bfloat162 hi = __float22bfloat162_rn(make_float2(f.z, f.w));
                uint2 u = { *(uint32_t*)&lo, *(uint32_t*)&hi };
                *(uint2*)&Xs[j][d4 * 4] = u;
            }
            __syncthreads();

            float acc[4][4] = {};
            #pragma unroll
            for (int ks = 0; ks < 4; ks++) {
                uint32_t a[4], b01[4], b23[4];
                ldsm_x4(a,   aAddr  + ks * 32);
                ldsm_x4(b01, bAddr1 + ks * 32);
                ldsm_x4(b23, bAddr2 + ks * 32);
                mma_bf16(acc[0], a, b01[0], b01[1]);
                mma_bf16(acc[1], a, b01[2], b01[3]);
                mma_bf16(acc[2], a, b23[0], b23[1]);
                mma_bf16(acc[3], a, b23[2], b23[3]);
            }

            float s0 = 0.f, s1 = 0.f;
            #pragma unroll
            for (int et = 0; et < 4; et++) {
                int e = eh + et * 8 + 2 * qc;
                s0 += aw_s[e]     * tanh_approx(acc[et][0] + ab_s[e]);
                s0 += aw_s[e + 1] * tanh_approx(acc[et][1] + ab_s[e + 1]);
                s1 += aw_s[e]     * tanh_approx(acc[et][2] + ab_s[e]);
                s1 += aw_s[e + 1] * tanh_approx(acc[et][3] + ab_s[e + 1]);
            }
            s0 += __shfl_xor_sync(0xffffffffu, s0, 1);
            s0 += __shfl_xor_sync(0xffffffffu, s0, 2);
            s1 += __shfl_xor_sync(0xffffffffu, s1, 1);
            s1 += __shfl_xor_sync(0xffffffffu, s1, 2);
            if (qc == 0) {
                spart[warp >> 2][jt + qr] = s0;
                spart[warp >> 2][jt + qr + 8] = s1;
            }
            __syncthreads();

            if (t < 64) {
                int j = jc * 64 + t;
                if (j >= i) {
                    float s = spart[0][t] + spart[1][t];
                    g_scores[(b * NN + i) * NN + j] = s;
                    g_scores[(b * NN + j) * NN + i] = s;
                }
            }
            __syncthreads();
        }
    }
}

// ---------------------------------------------------------------------------
// Phase 2 (tf32 tensor-core agg, proven fragment mapping): block = 16 rows,
// grid (32, NB). Softmax in registers per warp (2 rows). Per 64-k chunk:
// write tf32 attn slice As[16][68], stage X chunk Xs[64][72] (tf32), then
// m16n8k8 MMAs — A frags As[qr][k0+qc] etc., B frags Xs[k0+qc][nt*8+qr]
// (identical index pattern to the round-4 kScores that passed at 2.8e-7).
// h = agg@pw + x@pwo + biases; BN partials -> g_part.
// ---------------------------------------------------------------------------
__global__ __launch_bounds__(256) void kAgg(
    const float* __restrict__ x,
    const float* __restrict__ pw,
    const float* __restrict__ pwb,
    const float* __restrict__ pwo,
    const float* __restrict__ pwob)
{
    __shared__ uint32_t As[16][68];                 // tf32 attn slice [m][k]
    __shared__ __align__(16) uint32_t Xs[64][72];   // tf32 X chunk [k][d]
    __shared__ float agg_s[16][64];
    __shared__ float Xi[16][64];
    __shared__ float hs[16][64];

    const int t = threadIdx.x;
    const int warp = t >> 5, lane = t & 31;
    const int qr = lane >> 2, qc = lane & 3;
    const int nt = warp;                 // this warp's d-tile: nt*8..+8
    const int b = blockIdx.y;
    const int i0 = blockIdx.x * 16;
    const float* xb = x + b * NN * ND;

    // stage this block's 16 x-rows (fp32)
    for (int idx = t; idx < 16 * 64; idx += 256)
        Xi[idx >> 6][idx & 63] = xb[(i0 + (idx >> 6)) * ND + (idx & 63)];

    // softmax into registers: warp owns rows 2*warp, 2*warp+1
    float sv[2][16];
    #pragma unroll
    for (int rr = 0; rr < 2; rr++) {
        const float* srow = g_scores + (b * NN + i0 + 2 * warp + rr) * NN;
        float m = -1e30f;
        #pragma unroll
        for (int q = 0; q < 16; q++) {
            sv[rr][q] = srow[q * 32 + lane];
            m = fmaxf(m, sv[rr][q]);
        }
        #pragma unroll
        for (int o = 16; o > 0; o >>= 1)
            m = fmaxf(m, __shfl_xor_sync(0xffffffffu, m, o));
        float sum = 0.f;
        #pragma unroll
        for (int q = 0; q < 16; q++) {
            sv[rr][q] = __expf((sv[rr][q] - m) * TEMP_INV);
            sum += sv[rr][q];
        }
        #pragma unroll
        for (int o = 16; o > 0; o >>= 1)
            sum += __shfl_xor_sync(0xffffffffu, sum, o);
        float inv = 1.f / sum;
        #pragma unroll
        for (int q = 0; q < 16; q++) sv[rr][q] *= inv;
    }

    float acc[4] = {};
    for (int jc = 0; jc < 8; jc++) {
        __syncthreads();   // prev chunk's As/Xs fully consumed
        // attn slice for k = jc*64 .. +63  (sv[rr][2jc] -> col lane, etc.)
        As[2 * warp][lane]          = to_tf32(sv[0][2 * jc]);
        As[2 * warp][32 + lane]     = to_tf32(sv[0][2 * jc + 1]);
        As[2 * warp + 1][lane]      = to_tf32(sv[1][2 * jc]);
        As[2 * warp + 1][32 + lane] = to_tf32(sv[1][2 * jc + 1]);
        // X chunk
        #pragma unroll
        for (int k = 0; k < 4; k++) {
            int v = t + k * 256;
            int j = v >> 4, d4 = v & 15;
            float4 f = *(const float4*)&xb[(jc * 64 + j) * ND + d4 * 4];
            uint4 u = { to_tf32(f.x), to_tf32(f.y), to_tf32(f.z), to_tf32(f.w) };
            *(uint4*)&Xs[j][d4 * 4] = u;
        }
        __syncthreads();

        #pragma unroll
        for (int ks = 0; ks < 8; ks++) {
            const int k0 = ks * 8;
            uint32_t a0 = As[qr][k0 + qc];
            uint32_t a1 = As[qr + 8][k0 + qc];
            uint32_t a2 = As[qr][k0 + qc + 4];
            uint32_t a3 = As[qr + 8][k0 + qc + 4];
            uint32_t b0 = Xs[k0 + qc][nt * 8 + qr];
            uint32_t b1 = Xs[k0 + qc + 4][nt * 8 + qr];
            mma_tf32(acc, a0, a1, a2, a3, b0, b1);
        }
    }

    // scatter agg C-fragments (c0,c1 -> row qr; c2,c3 -> row qr+8)
    agg_s[qr][nt * 8 + qc * 2]         = acc[0];
    agg_s[qr][nt * 8 + qc * 2 + 1]     = acc[1];
    agg_s[qr + 8][nt * 8 + qc * 2]     = acc[2];
    agg_s[qr + 8][nt * 8 + qc * 2 + 1] = acc[3];
    __syncthreads();

    // h epilogue: thread -> (e = t&63, rows rg*4..+3)
    {
        int e = t & 63, rg = t >> 6;
        float h0 = pwb[e] + pwob[e];
        float hv[4] = { h0, h0, h0, h0 };
        #pragma unroll 8
        for (int d = 0; d < 64; d++) {
            float pwv = pw[d * 64 + e];
            float pov = pwo[d * 64 + e];
            #pragma unroll
            for (int k = 0; k < 4; k++) {
                int rr = rg * 4 + k;
                hv[k] += agg_s[rr][d] * pwv + Xi[rr][d] * pov;
            }
        }
        #pragma unroll
        for (int k = 0; k < 4; k++) {
            int rr = rg * 4 + k;
            g_h[(b * NN + i0 + rr) * ND + e] = hv[k];
            hs[rr][e] = hv[k];
        }
    }
    __syncthreads();

    // BN partials for this block's 16 rows
    if (t < 128) {
        int f = t & 63;
        float s = 0.f;
        if (t < 64) {
            #pragma unroll
            for (int w = 0; w < 16; w++) s += hs[w][f];
        } else {
            #pragma unroll
            for (int w = 0; w < 16; w++) { float v = hs[w][f]; s += v * v; }
        }
        g_part[(b * 32 + blockIdx.x) * 128 + t] = s;
    }
}

// ---------------------------------------------------------------------------
// kTail (one block per batch, 512 threads = one row each):
// stats reduce (64 partial blocks) -> BN+SELU+pool -> stable rank -> scatter.
// ---------------------------------------------------------------------------
__global__ __launch_bounds__(512) void kTail(
    const float* __restrict__ bn_g, const float* __restrict__ bn_b,
    const float* __restrict__ pool_w, const float* __restrict__ pool_b,
    float* __restrict__ out)
{
    __shared__ float red1[512], red2[512];
    __shared__ float a_s[64], c_s[64], pw_s[64];
    __shared__ float wv_s[512];

    const int t = threadIdx.x;
    const int b = blockIdx.x;

    {
        int f = t & 63, grp = t >> 6;
        float s = 0.f, q = 0.f;
        #pragma unroll
        for (int blk = grp; blk < 64; blk += 8) {
            s += g_part[blk * 128 + f];
            q += g_part[blk * 128 + 64 + f];
        }
        red1[t] = s;
        red2[t] = q;
        __syncthreads();
        if (t < 64) {
            float S = 0.f, Q = 0.f;
            #pragma unroll
            for (int g = 0; g < 8; g++) { S += red1[g * 64 + t]; Q += red2[g * 64 + t]; }
            float mean = S * (1.f / (NB * NN));
            float var = fmaxf(Q * (1.f / (NB * NN)) - mean * mean, 0.f);
            float a = rsqrtf(var + BN_EPS) * bn_g[t];
            a_s[t] = a;
            c_s[t] = bn_b[t] - mean * a;
            pw_s[t] = pool_w[t];
        }
        __syncthreads();
    }

    const float* hr = g_h + (b * NN + t) * ND;
    float4 hv[16];
    #pragma unroll
    for (int q = 0; q < 16; q++) hv[q] = *(const float4*)&hr[q * 4];

    float p = 0.f;
    #pragma unroll
    for (int q = 0; q < 16; q++) {
        #pragma unroll
        for (int c = 0; c < 4; c++) {
            int e = q * 4 + c;
            float v = (c == 0 ? hv[q].x : c == 1 ? hv[q].y : c == 2 ? hv[q].z : hv[q].w);
            float hn = v * a_s[e] + c_s[e];
            float s = hn > 0.f ? SELU_SCALE * hn
                               : SELU_SCALE * SELU_ALPHA * (__expf(hn) - 1.f);
            p += s * pw_s[e];
            if (c == 0) hv[q].x = s; else if (c == 1) hv[q].y = s;
            else if (c == 2) hv[q].z = s; else hv[q].w = s;
        }
    }
    float w = 1.f / (1.f + __expf(-(p + pool_b[0])));
    wv_s[t] = w;
    __syncthreads();

    int rank = 0;
    #pragma unroll 8
    for (int j = 0; j < NN; j++) {
        float u = wv_s[j];
        rank += (u > w) || (u == w && j < t);
    }

    if (rank < KN) {
        float* dp = out + (b * KN + rank) * ND;
        #pragma unroll
        for (int q = 0; q < 16; q++) {
            float4 o = hv[q];
            o.x *= w; o.y *= w; o.z *= w; o.w *= w;
            *(float4*)&dp[q * 4] = o;
        }
    }
}

// ---------------------------------------------------------------------------
// Launch (graph-capturable). 2 dummies -> ncu's captured launch (#4) = kAgg.
// ---------------------------------------------------------------------------
extern "C" void kernel_launch(void* const* d_in, const int* in_sizes, int n_in,
                              void* d_out, int out_size)
{
    const float* x     = (const float*)d_in[0];
    const float* apw   = (const float*)d_in[1];
    const float* apb   = (const float*)d_in[2];
    const float* awt   = (const float*)d_in[3];
    const float* pw    = (const float*)d_in[4];
    const float* pwb   = (const float*)d_in[5];
    const float* pwo   = (const float*)d_in[6];
    const float* pwob  = (const float*)d_in[7];
    const float* bn_g  = (const float*)d_in[8];
    const float* bn_b  = (const float*)d_in[9];
    const float* poolw = (const float*)d_in[10];
    const float* poolb = (const float*)d_in[11];
    float* out = (float*)d_out;

    kDummy<<<1, 32>>>();
    kDummy<<<1, 32>>>();
    kScores<<<dim3(NN / 2, NB), 256>>>(x, apw, apb, awt);
    kAgg<<<dim3(NN / 16, NB), 256>>>(x, pw, pwb, pwo, pwob);
    kTail<<<NB, 512>>>(bn_g, bn_b, poolw, poolb, out);
}

// round 12
// speedup vs baseline: 2.5842x; 1.1167x over previous
#include <cuda_runtime.h>
#include <cuda_bf16.h>
#include <cstdint>

// ---------------------------------------------------------------------------
// B=2, N=512, D_IN=D_OUT=64, TEMP=100, POOL_K=0.5 -> kn=256
// ---------------------------------------------------------------------------
#define NB 2
#define NN 512
#define ND 64
#define KN 256
#define TEMP_INV (1.0f/100.0f)
#define BN_EPS 1e-5f
#define SELU_SCALE 1.0507009873554804934193349852946f
#define SELU_ALPHA 1.6732632423543772848170429916717f

__device__ float g_scores[NB*NN*NN];
__device__ float g_h[NB*NN*ND];
__device__ float g_part[128*128];   // per-kAgg-block partial BN stats

__device__ __forceinline__ float tanh_approx(float x) {
    float r;
    asm("tanh.approx.f32 %0, %1;" : "=f"(r) : "f"(x));
    return r;
}
__device__ __forceinline__ uint32_t to_tf32(float f) {
    uint32_t u;
    asm("cvt.rna.tf32.f32 %0, %1;" : "=r"(u) : "f"(f));
    return u;
}
__device__ __forceinline__ void mma_tf32(float c[4], uint32_t a0, uint32_t a1,
                                         uint32_t a2, uint32_t a3,
                                         uint32_t b0, uint32_t b1) {
    asm("mma.sync.aligned.m16n8k8.row.col.f32.tf32.tf32.f32 "
        "{%0,%1,%2,%3}, {%4,%5,%6,%7}, {%8,%9}, {%0,%1,%2,%3};"
        : "+f"(c[0]), "+f"(c[1]), "+f"(c[2]), "+f"(c[3])
        : "r"(a0), "r"(a1), "r"(a2), "r"(a3), "r"(b0), "r"(b1));
}
__device__ __forceinline__ void mma_bf16(float c[4], const uint32_t a[4],
                                         uint32_t b0, uint32_t b1) {
    asm("mma.sync.aligned.m16n8k16.row.col.f32.bf16.bf16.f32 "
        "{%0,%1,%2,%3}, {%4,%5,%6,%7}, {%8,%9}, {%0,%1,%2,%3};"
        : "+f"(c[0]), "+f"(c[1]), "+f"(c[2]), "+f"(c[3])
        : "r"(a[0]), "r"(a[1]), "r"(a[2]), "r"(a[3]), "r"(b0), "r"(b1));
}
__device__ __forceinline__ void ldsm_x4(uint32_t r[4], uint32_t addr) {
    asm volatile("ldmatrix.sync.aligned.m8n8.x4.shared.b16 {%0,%1,%2,%3}, [%4];"
        : "=r"(r[0]), "=r"(r[1]), "=r"(r[2]), "=r"(r[3]) : "r"(addr));
}

// ---------------------------------------------------------------------------
// Phase 1 (bf16 tensor cores + ldmatrix, proven): scores upper triangle via
// symmetry. Unchanged from round 8/11.
// ---------------------------------------------------------------------------
__global__ __launch_bounds__(256) void kScores(
    const float* __restrict__ x,
    const float* __restrict__ apw,
    const float* __restrict__ apb,
    const float* __restrict__ awt)
{
    __shared__ __align__(16) __nv_bfloat16 Xs[64][72];  // [j][d]
    __shared__ __align__(16) __nv_bfloat16 Wt[64][72];  // [e][d]
    __shared__ float spart[2][64];
    __shared__ float xi_s[64], ab_s[64], aw_s[64];

    const int t = threadIdx.x;
    const int p = blockIdx.x;
    const int b = blockIdx.y;
    const float* xb = x + b * NN * ND;

    const int warp = t >> 5, lane = t & 31;
    const int jt = (warp & 3) * 16;
    const int eh = (warp >> 2) * 32;
    const int qr = lane >> 2, qc = lane & 3;

    if (t < 64) { ab_s[t] = apb[t]; aw_s[t] = awt[t]; }

    const uint32_t xsBase = (uint32_t)__cvta_generic_to_shared(&Xs[0][0]);
    const uint32_t wtBase = (uint32_t)__cvta_generic_to_shared(&Wt[0][0]);
    const uint32_t aAddr = xsBase + (jt + (lane & 15)) * 144 + (lane >> 4) * 16;
    const uint32_t bAddr1 = wtBase +
        (eh + (lane >> 4) * 8 + (lane & 7)) * 144 + ((lane >> 3) & 1) * 16;
    const uint32_t bAddr2 = bAddr1 + 16 * 144;

    #pragma unroll 1
    for (int r = 0; r < 2; r++) {
        const int i = r ? (NN - 1 - p) : p;
        __syncthreads();
        if (t < 64) xi_s[t] = xb[i * ND + t];
        __syncthreads();

        #pragma unroll
        for (int k = 0; k < 16; k++) {
            int idx = t + k * 256;
            int d = idx >> 6, e = idx & 63;
            Wt[e][d] = __float2bfloat16(xi_s[d] * apw[idx]);
        }

        for (int jc = i >> 6; jc < 8; jc++) {
            #pragma unroll
            for (int k = 0; k < 4; k++) {
                int v = t + k * 256;
                int j = v >> 4, d4 = v & 15;
                float4 f = *(const float4*)&xb[(jc * 64 + j) * ND + d4 * 4];
                __nv_bfloat162 lo = __float22bfloat162_rn(make_float2(f.x, f.y));
                __nv_bfloat162 hi = __float22bfloat162_rn(make_float2(f.z, f.w));
                uint2 u = { *(uint32_t*)&lo, *(uint32_t*)&hi };
                *(uint2*)&Xs[j][d4 * 4] = u;
            }
            __syncthreads();

            float acc[4][4] = {};
            #pragma unroll
            for (int ks = 0; ks < 4; ks++) {
                uint32_t a[4], b01[4], b23[4];
                ldsm_x4(a,   aAddr  + ks * 32);
                ldsm_x4(b01, bAddr1 + ks * 32);
                ldsm_x4(b23, bAddr2 + ks * 32);
                mma_bf16(acc[0], a, b01[0], b01[1]);
                mma_bf16(acc[1], a, b01[2], b01[3]);
                mma_bf16(acc[2], a, b23[0], b23[1]);
                mma_bf16(acc[3], a, b23[2], b23[3]);
            }

            float s0 = 0.f, s1 = 0.f;
            #pragma unroll
            for (int et = 0; et < 4; et++) {
                int e = eh + et * 8 + 2 * qc;
                s0 += aw_s[e]     * tanh_approx(acc[et][0] + ab_s[e]);
                s0 += aw_s[e + 1] * tanh_approx(acc[et][1] + ab_s[e + 1]);
                s1 += aw_s[e]     * tanh_approx(acc[et][2] + ab_s[e]);
                s1 += aw_s[e + 1] * tanh_approx(acc[et][3] + ab_s[e + 1]);
            }
            s0 += __shfl_xor_sync(0xffffffffu, s0, 1);
            s0 += __shfl_xor_sync(0xffffffffu, s0, 2);
            s1 += __shfl_xor_sync(0xffffffffu, s1, 1);
            s1 += __shfl_xor_sync(0xffffffffu, s1, 2);
            if (qc == 0) {
                spart[warp >> 2][jt + qr] = s0;
                spart[warp >> 2][jt + qr + 8] = s1;
            }
            __syncthreads();

            if (t < 64) {
                int j = jc * 64 + t;
                if (j >= i) {
                    float s = spart[0][t] + spart[1][t];
                    g_scores[(b * NN + i) * NN + j] = s;
                    g_scores[(b * NN + j) * NN + i] = s;
                }
            }
            __syncthreads();
        }
    }
}

// ---------------------------------------------------------------------------
// Phase 2 v2: 8 rows/block, grid (64, NB) = 128 blocks (one per SM).
// - softmax per warp (1 row), NO max pass: |score|/TEMP <= ~0.07 so exp is
//   safe; normalization makes it mathematically identical to the reference.
// - jc loop FULLY UNROLLED -> sv[] stays in registers (round-11 version
//   spilled it to local memory via dynamic indexing).
// - m16n8k8 tf32 MMA, A-rows 8..15 zero-filled once (acc[2..3] discarded).
//   Fragment index pattern identical to the round-11 passing kernel.
// ---------------------------------------------------------------------------
__global__ __launch_bounds__(256) void kAgg(
    const float* __restrict__ x,
    const float* __restrict__ pw,
    const float* __restrict__ pwb,
    const float* __restrict__ pwo,
    const float* __restrict__ pwob)
{
    __shared__ uint32_t As[16][68];                 // tf32 attn slice [m][k]
    __shared__ __align__(16) uint32_t Xs[64][72];   // tf32 X chunk [k][d]
    __shared__ float agg_s[8][64];
    __shared__ float Xi[8][64];
    __shared__ float hs[8][64];

    const int t = threadIdx.x;
    const int warp = t >> 5, lane = t & 31;
    const int qr = lane >> 2, qc = lane & 3;
    const int nt = warp;                 // this warp's d-tile: nt*8..+8
    const int b = blockIdx.y;
    const int i0 = blockIdx.x * 8;
    const float* xb = x + b * NN * ND;

    // zero A-rows 8..15 (cols 0..63; fragments only read cols < 64)
    for (int idx = t; idx < 8 * 64; idx += 256)
        As[8 + (idx >> 6)][idx & 63] = 0;

    // stage this block's 8 x-rows (fp32)
    for (int idx = t; idx < 8 * 64; idx += 256)
        Xi[idx >> 6][idx & 63] = xb[(i0 + (idx >> 6)) * ND + (idx & 63)];

    // softmax (no max pass): warp owns row i0+warp
    float sv[16];
    {
        const float* srow = g_scores + (b * NN + i0 + warp) * NN;
        float sum = 0.f;
        #pragma unroll
        for (int q = 0; q < 16; q++) {
            sv[q] = __expf(srow[q * 32 + lane] * TEMP_INV);
            sum += sv[q];
        }
        #pragma unroll
        for (int o = 16; o > 0; o >>= 1)
            sum += __shfl_xor_sync(0xffffffffu, sum, o);
        float inv = 1.f / sum;
        #pragma unroll
        for (int q = 0; q < 16; q++) sv[q] *= inv;
    }

    float acc[4] = {};
    #pragma unroll
    for (int jc = 0; jc < 8; jc++) {
        __syncthreads();   // prev chunk's As/Xs fully consumed
        As[warp][lane]      = to_tf32(sv[2 * jc]);
        As[warp][32 + lane] = to_tf32(sv[2 * jc + 1]);
        #pragma unroll
        for (int k = 0; k < 4; k++) {
            int v = t + k * 256;
            int j = v >> 4, d4 = v & 15;
            float4 f = *(const float4*)&xb[(jc * 64 + j) * ND + d4 * 4];
            uint4 u = { to_tf32(f.x), to_tf32(f.y), to_tf32(f.z), to_tf32(f.w) };
            *(uint4*)&Xs[j][d4 * 4] = u;
        }
        __syncthreads();

        #pragma unroll
        for (int ks = 0; ks < 8; ks++) {
            const int k0 = ks * 8;
            uint32_t a0 = As[qr][k0 + qc];
            uint32_t a1 = As[qr + 8][k0 + qc];        // zero rows
            uint32_t a2 = As[qr][k0 + qc + 4];
            uint32_t a3 = As[qr + 8][k0 + qc + 4];    // zero rows
            uint32_t b0 = Xs[k0 + qc][nt * 8 + qr];
            uint32_t b1 = Xs[k0 + qc + 4][nt * 8 + qr];
            mma_tf32(acc, a0, a1, a2, a3, b0, b1);
        }
    }

    // scatter valid agg C-fragments (rows 0..7)
    agg_s[qr][nt * 8 + qc * 2]     = acc[0];
    agg_s[qr][nt * 8 + qc * 2 + 1] = acc[1];
    __syncthreads();

    // h epilogue: thread -> (e = t&63, rows rg*2, rg*2+1)
    {
        int e = t & 63, rg = t >> 6;
        float h0 = pwb[e] + pwob[e];
        float hv[2] = { h0, h0 };
        #pragma unroll 8
        for (int d = 0; d < 64; d++) {
            float pwv = pw[d * 64 + e];
            float pov = pwo[d * 64 + e];
            #pragma unroll
            for (int k = 0; k < 2; k++) {
                int rr = rg * 2 + k;
                hv[k] += agg_s[rr][d] * pwv + Xi[rr][d] * pov;
            }
        }
        #pragma unroll
        for (int k = 0; k < 2; k++) {
            int rr = rg * 2 + k;
            g_h[(b * NN + i0 + rr) * ND + e] = hv[k];
            hs[rr][e] = hv[k];
        }
    }
    __syncthreads();

    // BN partials for this block's 8 rows
    if (t < 128) {
        int f = t & 63;
        float s = 0.f;
        if (t < 64) {
            #pragma unroll
            for (int w = 0; w < 8; w++) s += hs[w][f];
        } else {
            #pragma unroll
            for (int w = 0; w < 8; w++) { float v = hs[w][f]; s += v * v; }
        }
        g_part[(b * 64 + blockIdx.x) * 128 + t] = s;
    }
}

// ---------------------------------------------------------------------------
// kTail (one block per batch, 512 threads = one row each):
// stats reduce (128 partial blocks) -> BN+SELU+pool -> stable rank -> scatter.
// ---------------------------------------------------------------------------
__global__ __launch_bounds__(512) void kTail(
    const float* __restrict__ bn_g, const float* __restrict__ bn_b,
    const float* __restrict__ pool_w, const float* __restrict__ pool_b,
    float* __restrict__ out)
{
    __shared__ float red1[512], red2[512];
    __shared__ float a_s[64], c_s[64], pw_s[64];
    __shared__ float wv_s[512];

    const int t = threadIdx.x;
    const int b = blockIdx.x;

    {
        int f = t & 63, grp = t >> 6;
        float s = 0.f, q = 0.f;
        #pragma unroll 4
        for (int blk = grp; blk < 128; blk += 8) {
            s += g_part[blk * 128 + f];
            q += g_part[blk * 128 + 64 + f];
        }
        red1[t] = s;
        red2[t] = q;
        __syncthreads();
        if (t < 64) {
            float S = 0.f, Q = 0.f;
            #pragma unroll
            for (int g = 0; g < 8; g++) { S += red1[g * 64 + t]; Q += red2[g * 64 + t]; }
            float mean = S * (1.f / (NB * NN));
            float var = fmaxf(Q * (1.f / (NB * NN)) - mean * mean, 0.f);
            float a = rsqrtf(var + BN_EPS) * bn_g[t];
            a_s[t] = a;
            c_s[t] = bn_b[t] - mean * a;
            pw_s[t] = pool_w[t];
        }
        __syncthreads();
    }

    const float* hr = g_h + (b * NN + t) * ND;
    float4 hv[16];
    #pragma unroll
    for (int q = 0; q < 16; q++) hv[q] = *(const float4*)&hr[q * 4];

    float p = 0.f;
    #pragma unroll
    for (int q = 0; q < 16; q++) {
        #pragma unroll
        for (int c = 0; c < 4; c++) {
            int e = q * 4 + c;
            float v = (c == 0 ? hv[q].x : c == 1 ? hv[q].y : c == 2 ? hv[q].z : hv[q].w);
            float hn = v * a_s[e] + c_s[e];
            float s = hn > 0.f ? SELU_SCALE * hn
                               : SELU_SCALE * SELU_ALPHA * (__expf(hn) - 1.f);
            p += s * pw_s[e];
            if (c == 0) hv[q].x = s; else if (c == 1) hv[q].y = s;
            else if (c == 2) hv[q].z = s; else hv[q].w = s;
        }
    }
    float w = 1.f / (1.f + __expf(-(p + pool_b[0])));
    wv_s[t] = w;
    __syncthreads();

    int rank = 0;
    #pragma unroll 8
    for (int j = 0; j < NN; j++) {
        float u = wv_s[j];
        rank += (u > w) || (u == w && j < t);
    }

    if (rank < KN) {
        float* dp = out + (b * KN + rank) * ND;
        #pragma unroll
        for (int q = 0; q < 16; q++) {
            float4 o = hv[q];
            o.x *= w; o.y *= w; o.z *= w; o.w *= w;
            *(float4*)&dp[q * 4] = o;
        }
    }
}

// ---------------------------------------------------------------------------
// Launch (graph-capturable): 3 kernels, no dummies.
// ---------------------------------------------------------------------------
extern "C" void kernel_launch(void* const* d_in, const int* in_sizes, int n_in,
                              void* d_out, int out_size)
{
    const float* x     = (const float*)d_in[0];
    const float* apw   = (const float*)d_in[1];
    const float* apb   = (const float*)d_in[2];
    const float* awt   = (const float*)d_in[3];
    const float* pw    = (const float*)d_in[4];
    const float* pwb   = (const float*)d_in[5];
    const float* pwo   = (const float*)d_in[6];
    const float* pwob  = (const float*)d_in[7];
    const float* bn_g  = (const float*)d_in[8];
    const float* bn_b  = (const float*)d_in[9];
    const float* poolw = (const float*)d_in[10];
    const float* poolb = (const float*)d_in[11];
    float* out = (float*)d_out;

    kScores<<<dim3(NN / 2, NB), 256>>>(x, apw, apb, awt);
    kAgg<<<dim3(NN / 8, NB), 256>>>(x, pw, pwb, pwo, pwob);
    kTail<<<NB, 512>>>(bn_g, bn_b, poolw, poolb, out);
}